// round 10
// baseline (speedup 1.0000x reference)
#include <cuda_runtime.h>
#include <math.h>
#include <stdint.h>

#define D_MODEL 1024
#define N_HEAD  16
#define D_HEAD  64
#define N_CTX   2048
#define BATCH   2
#define MTOT    (BATCH * N_CTX)   /* 4096 rows */

// ---------------- scratch ----------------
__device__ float g_q[MTOT * D_MODEL];
__device__ float g_k[MTOT * D_MODEL];
__device__ float g_v[MTOT * D_MODEL];
__device__ float g_z[MTOT * D_MODEL];
__device__ float g_cos[N_CTX * 32];
__device__ float g_sin[N_CTX * 32];

// ---------------- helpers ----------------
__device__ __forceinline__ float ftf(float x) {
    uint32_t u;
    asm("cvt.rna.tf32.f32 %0, %1;" : "=r"(u) : "f"(x));
    return __uint_as_float(u);
}

__device__ __forceinline__ void mma8(float c[4], const float a[4], const float b[2]) {
    asm volatile(
        "mma.sync.aligned.m16n8k8.row.col.f32.tf32.tf32.f32 "
        "{%0,%1,%2,%3}, {%4,%5,%6,%7}, {%8,%9}, {%0,%1,%2,%3};\n"
        : "+f"(c[0]), "+f"(c[1]), "+f"(c[2]), "+f"(c[3])
        : "r"(__float_as_uint(a[0])), "r"(__float_as_uint(a[1])),
          "r"(__float_as_uint(a[2])), "r"(__float_as_uint(a[3])),
          "r"(__float_as_uint(b[0])), "r"(__float_as_uint(b[1])));
}

// ---------------- RoPE table ----------------
__global__ void rope_cache_kernel() {
    int i = blockIdx.x * blockDim.x + threadIdx.x;
    int t = i >> 5;
    int j = i & 31;
    float invf = (float)pow(10000.0, -(double)j / 32.0);
    double ang = (double)t * (double)invf;
    double sv, cv;
    sincos(ang, &sv, &cv);
    g_cos[i] = (float)cv;
    g_sin[i] = (float)sv;
}

// ---------------- TF32 GEMM (proven core), multi-job, fused norm+rope epilogue ----------------
struct GemmJobs {
    const float* W[3];
    const float* bias[3];
    const float* res[3];
    float*       out[3];
    int          norm[3];   // 1 => apply rmsnorm+rope in epilogue (q/k jobs)
};

__global__ __launch_bounds__(256, 2)
void gemm_tc_kernel(const float* __restrict__ A, GemmJobs jobs,
                    const float* __restrict__ nw, int M, int N, int K)
{
    __shared__ __align__(16) float As[4096];
    __shared__ __align__(16) float Bs[4096];
    float4* As4 = (float4*)As;
    float4* Bs4 = (float4*)Bs;

    const int z = blockIdx.z;
    const float* W    = jobs.W[z];
    const float* bias = jobs.bias[z];
    const float* res  = jobs.res[z];
    float*       C    = jobs.out[z];
    const int    donorm = jobs.norm[z];

    const int tid = threadIdx.x;
    const int lane = tid & 31;
    const int wid = tid >> 5;
    const int wm = wid & 3, wn = wid >> 2;
    const int m0 = blockIdx.y * 128, n0 = blockIdx.x * 128;

    const int amt = tid >> 5, ag = (tid >> 2) & 7, aks = tid & 3;
    const float* Ap = A + (size_t)(m0 + amt * 16 + ag) * K + aks * 8;
    const int bnt = ((tid >> 5) << 1) | (tid & 1);
    const int bg = (tid >> 2) & 7;
    const int bksp = (tid >> 1) & 1;
    const int bxor = bksp | ((bnt & 1) << 1);
    const float* Wp = W + (size_t)(n0 + bnt * 8 + bg) * K + bksp * 16;

    float acc[2][8][4];
#pragma unroll
    for (int mi = 0; mi < 2; mi++)
#pragma unroll
        for (int ni = 0; ni < 8; ni++)
#pragma unroll
            for (int e = 0; e < 4; e++) acc[mi][ni][e] = 0.f;

    for (int kt = 0; kt < K; kt += 32) {
        float a0[4], a1[4], a2[4], a3[4];
        float w0[4], w1[4], w2[4], w3[4];
        {
            float4 v0 = *(const float4*)(Ap + kt);
            float4 v1 = *(const float4*)(Ap + kt + 4);
            float4 v2 = *(const float4*)(Ap + kt + (size_t)8 * K);
            float4 v3 = *(const float4*)(Ap + kt + (size_t)8 * K + 4);
            a0[0]=v0.x;a0[1]=v0.y;a0[2]=v0.z;a0[3]=v0.w;
            a1[0]=v1.x;a1[1]=v1.y;a1[2]=v1.z;a1[3]=v1.w;
            a2[0]=v2.x;a2[1]=v2.y;a2[2]=v2.z;a2[3]=v2.w;
            a3[0]=v3.x;a3[1]=v3.y;a3[2]=v3.z;a3[3]=v3.w;
            float4 u0 = *(const float4*)(Wp + kt);
            float4 u1 = *(const float4*)(Wp + kt + 4);
            float4 u2 = *(const float4*)(Wp + kt + 8);
            float4 u3 = *(const float4*)(Wp + kt + 12);
            w0[0]=u0.x;w0[1]=u0.y;w0[2]=u0.z;w0[3]=u0.w;
            w1[0]=u1.x;w1[1]=u1.y;w1[2]=u1.z;w1[3]=u1.w;
            w2[0]=u2.x;w2[1]=u2.y;w2[2]=u2.z;w2[3]=u2.w;
            w3[0]=u3.x;w3[1]=u3.y;w3[2]=u3.z;w3[3]=u3.w;
        }
        __syncthreads();
#pragma unroll
        for (int t = 0; t < 4; t++) {
            As4[(aks * 8 + amt) * 32 + ag * 4 + (t ^ aks)] =
                make_float4(ftf(a0[t]), ftf(a2[t]), ftf(a1[t]), ftf(a3[t]));
            Bs4[(bksp * 16 + bnt) * 32 + bg * 4 + (t ^ bxor)] =
                make_float4(ftf(w0[t]), ftf(w1[t]), ftf(w2[t]), ftf(w3[t]));
        }
        __syncthreads();
#pragma unroll
        for (int ksp = 0; ksp < 2; ksp++) {
            float4 bb[8];
#pragma unroll
            for (int ni = 0; ni < 8; ni++) {
                int nt = wn * 8 + ni;
                int xv = ksp | ((nt & 1) << 1);
                int lp = (lane & ~3) | ((lane & 3) ^ xv);
                bb[ni] = Bs4[(ksp * 16 + nt) * 32 + lp];
            }
#pragma unroll
            for (int kh = 0; kh < 2; kh++) {
                int ks = ksp * 2 + kh;
                int lpa = (lane & ~3) | ((lane & 3) ^ ks);
                float a[2][4];
#pragma unroll
                for (int mi = 0; mi < 2; mi++) {
                    float4 aa = As4[(ks * 8 + wm * 2 + mi) * 32 + lpa];
                    a[mi][0] = aa.x; a[mi][1] = aa.y; a[mi][2] = aa.z; a[mi][3] = aa.w;
                }
#pragma unroll
                for (int mi = 0; mi < 2; mi++)
#pragma unroll
                    for (int ni = 0; ni < 8; ni++) {
                        float b[2];
                        if (kh == 0) { b[0] = bb[ni].x; b[1] = bb[ni].y; }
                        else         { b[0] = bb[ni].z; b[1] = bb[ni].w; }
                        mma8(acc[mi][ni], a[mi], b);
                    }
            }
        }
    }

    const int g = lane >> 2, t = lane & 3;
    if (donorm) {
        // rows of warp = one head's 64 cols; rmsnorm (reduce over t-quad) + rope, in epilogue
#pragma unroll
        for (int mi = 0; mi < 2; mi++) {
#pragma unroll
            for (int h = 0; h < 2; h++) {
                int m = m0 + wm * 32 + mi * 16 + h * 8 + g;
                int s = m & (N_CTX - 1);
                float v0[8], v1[8];
                float ss = 0.f;
#pragma unroll
                for (int ni = 0; ni < 8; ni++) {
                    int n = n0 + wn * 64 + ni * 8 + 2 * t;
                    float e0 = acc[mi][ni][h * 2 + 0] + bias[n];
                    float e1 = acc[mi][ni][h * 2 + 1] + bias[n + 1];
                    v0[ni] = e0; v1[ni] = e1;
                    ss = fmaf(e0, e0, fmaf(e1, e1, ss));
                }
                ss += __shfl_xor_sync(0xffffffffu, ss, 1);
                ss += __shfl_xor_sync(0xffffffffu, ss, 2);
                float r = rsqrtf(ss * (1.0f / 64.0f) + 1.1920929e-07f);
#pragma unroll
                for (int ni = 0; ni < 8; ni++) {
                    int d = ni * 8 + 2 * t;           // within-head index (even)
                    float y0 = v0[ni] * r * nw[d];
                    float y1 = v1[ni] * r * nw[d + 1];
                    int j0 = d & 31, j1 = (d + 1) & 31;
                    float o0 = y0 * g_cos[s * 32 + j0] - y1 * g_sin[s * 32 + j0];
                    float o1 = y1 * g_cos[s * 32 + j1] + y0 * g_sin[s * 32 + j1];
                    int n = n0 + wn * 64 + d;
                    *(float2*)&C[(size_t)m * N + n] = make_float2(o0, o1);
                }
            }
        }
    } else {
#pragma unroll
        for (int mi = 0; mi < 2; mi++) {
#pragma unroll
            for (int h = 0; h < 2; h++) {
                int m = m0 + wm * 32 + mi * 16 + h * 8 + g;
#pragma unroll
                for (int ni = 0; ni < 8; ni++) {
                    int n = n0 + wn * 64 + ni * 8 + 2 * t;
                    float2 v = make_float2(acc[mi][ni][h * 2 + 0], acc[mi][ni][h * 2 + 1]);
                    if (bias) { v.x += bias[n]; v.y += bias[n + 1]; }
                    if (res) {
                        float2 r = *(const float2*)&res[(size_t)m * N + n];
                        v.x += r.x; v.y += r.y;
                    }
                    *(float2*)&C[(size_t)m * N + n] = v;
                }
            }
        }
    }
}

// ---------------- fused quadratic causal attention, TF32 mma ----------------
// CTA: 128 threads (4 warps), q-tile 128; warp owns 32 q-rows x full 64-k.
// Double-buffered K/V (one barrier per k-tile: early warps start next tile's
// LDG+STS while late warps still compute). Shuffle-free P via V row permutation.
#define ATTN_SMEM (24576 * 4)   /* 96 KB: Qs 32KB | Ks[2] 32KB | Vs[2] 32KB */

__global__ __launch_bounds__(128)
void attn_tc_kernel(const float* __restrict__ Q, const float* __restrict__ Kg,
                    const float* __restrict__ V, float* __restrict__ Z)
{
    extern __shared__ float sm[];
    float4* Qs4 = (float4*)sm;               // [ks8][mt8][lane32] float4 frags

    const int tid = threadIdx.x;
    const int lane = tid & 31;
    const int wp = tid >> 5;                 // warp 0..3
    const int g = lane >> 2, t = lane & 3;
    const int bh = blockIdx.y;
    const int b = bh >> 4, h = bh & 15;
    const int jt = (int)gridDim.x - 1 - (int)blockIdx.x;   // big tiles first
    const size_t base = (size_t)(b * N_CTX) * D_MODEL + h * 64;
    const int nkt = 2 * jt + 2;

    // ---- Q tile (128 x 64) -> fragment-major smem, once ----
    {
        const int r0 = tid >> 4, c4 = tid & 15;
        const int qks = c4 >> 1, th = c4 & 1;
        const int kx = qks & 3;
#pragma unroll
        for (int j = 0; j < 16; j++) {
            int r = 8 * j + r0;
            int mt = r >> 4, gg = r & 15;
            int comp = (gg >> 3) + 2 * th;
            int gq = gg & 7;
            float4 qv = *(const float4*)&Q[base + (size_t)(jt * 128 + r) * D_MODEL + c4 * 4];
            float vals[4] = {qv.x, qv.y, qv.z, qv.w};
            float* dst = (float*)Qs4 + ((qks * 8 + mt) * 32) * 4 + comp;
#pragma unroll
            for (int i = 0; i < 4; i++)
                dst[(4 * gq + (i ^ kx)) * 4] = ftf(vals[i]);
        }
    }

    float zacc[2][8][4];
#pragma unroll
    for (int mm = 0; mm < 2; mm++)
#pragma unroll
        for (int i = 0; i < 8; i++)
#pragma unroll
            for (int j = 0; j < 4; j++) zacc[mm][i][j] = 0.f;

    // K loader: rows krow0+8j, cols kcol4*4..+3
    const int krow0 = tid >> 4, kcol4 = tid & 15;
    const int kksp = kcol4 >> 2, kcomp = kcol4 & 3;
    // V loader: row vrow, cols (vh + 2j)*4..+3, with within-8 row permutation
    const int vrow = tid & 63, vh = tid >> 6;
    const int vcp = vrow >> 4;
    const int vrr = vrow & 7;
    const int vkh = (vrow >> 3) & 1;
    const int vtt = vrr >> 1;
    const int vcomp = (vrr & 1) | (vkh << 1);
    const int vg0 = vh * 4;
    const int vsw = vtt ^ (vcp & 3);

    const float* kbase = Kg + base;
    const float* vbase = V + base;

    const float inv64 = 1.0f / 64.0f;
    const int qbase = jt * 128 + wp * 32;

    for (int kt = 0; kt < nkt; ++kt) {
        const int ktb = kt * 64;
        const int bu = kt & 1;
        float* KsF = sm + 8192  + bu * 4096;
        float* VsF = sm + 16384 + bu * 4096;

        // ---- K tile -> fragment-major (writes buf bu; safe: readers of this
        // buffer from iter kt-2 are separated by the barriers at kt-1 and kt) ----
#pragma unroll
        for (int j = 0; j < 8; j++) {
            float4 kv = *(const float4*)&kbase[(size_t)(ktb + krow0 + 8 * j) * D_MODEL + kcol4 * 4];
            int bb = (kksp * 8 + j) * 32 + krow0 * 4;
            KsF[(bb + (0 ^ kksp)) * 4 + kcomp] = ftf(kv.x);
            KsF[(bb + (1 ^ kksp)) * 4 + kcomp] = ftf(kv.y);
            KsF[(bb + (2 ^ kksp)) * 4 + kcomp] = ftf(kv.z);
            KsF[(bb + (3 ^ kksp)) * 4 + kcomp] = ftf(kv.w);
        }
        // ---- V tile -> fragment-major (k-permuted, cp-xor swizzled) ----
#pragma unroll
        for (int j = 0; j < 8; j++) {
            float4 vv = *(const float4*)&vbase[(size_t)(ktb + vrow) * D_MODEL + (vh + 2 * j) * 4];
            int bb = (vcp * 8 + j) * 32 + vg0 * 4 + vsw;
            VsF[(bb + 0)  * 4 + vcomp] = ftf(vv.x);
            VsF[(bb + 4)  * 4 + vcomp] = ftf(vv.y);
            VsF[(bb + 8)  * 4 + vcomp] = ftf(vv.z);
            VsF[(bb + 12) * 4 + vcomp] = ftf(vv.w);
        }
        __syncthreads();   // buf bu fully written (also orders Q store at kt=0)

        const float4* KsP = (const float4*)KsF;
        const float4* VsP = (const float4*)VsF;

        // ---- GEMM1: S[32 x 64] per warp ----
        float sacc[2][8][4];
#pragma unroll
        for (int mm = 0; mm < 2; mm++)
#pragma unroll
            for (int i = 0; i < 8; i++)
#pragma unroll
                for (int j = 0; j < 4; j++) sacc[mm][i][j] = 0.f;

#pragma unroll
        for (int ksp = 0; ksp < 4; ksp++) {
            int slot = (lane & 28) | ((lane & 3) ^ ksp);
            float4 kb[8];
#pragma unroll
            for (int nt = 0; nt < 8; nt++)
                kb[nt] = KsP[(ksp * 8 + nt) * 32 + slot];
#pragma unroll
            for (int kh = 0; kh < 2; kh++) {
                int ks = ksp * 2 + kh;
                int qslot = (lane & 28) | ((lane & 3) ^ (ks & 3));
                float4 qa0 = Qs4[(ks * 8 + wp * 2 + 0) * 32 + qslot];
                float4 qa1 = Qs4[(ks * 8 + wp * 2 + 1) * 32 + qslot];
                float a0[4] = {qa0.x, qa0.y, qa0.z, qa0.w};
                float a1[4] = {qa1.x, qa1.y, qa1.z, qa1.w};
#pragma unroll
                for (int nt = 0; nt < 8; nt++) {
                    float bfr[2];
                    if (kh == 0) { bfr[0] = kb[nt].x; bfr[1] = kb[nt].y; }
                    else         { bfr[0] = kb[nt].z; bfr[1] = kb[nt].w; }
                    mma8(sacc[0][nt], a0, bfr);
                    mma8(sacc[1][nt], a1, bfr);
                }
            }
        }

        // ---- P = (S/64)^2 * causal; direct C->A rename; GEMM2 ----
#pragma unroll
        for (int cp = 0; cp < 4; cp++) {
            int vslot = (lane & 28) | ((lane & 3) ^ (cp & 3));
            float4 vb[8];
#pragma unroll
            for (int dn = 0; dn < 8; dn++)
                vb[dn] = VsP[(cp * 8 + dn) * 32 + vslot];
#pragma unroll
            for (int kh = 0; kh < 2; kh++) {
                int c = cp * 2 + kh;
                int kc = ktb + c * 8 + 2 * t;
#pragma unroll
                for (int mm = 0; mm < 2; mm++) {
                    int qr0 = qbase + mm * 16 + g;
                    int qr1 = qr0 + 8;
                    float s0 = sacc[mm][c][0] * inv64; s0 *= s0; if (kc > qr0)     s0 = 0.f;
                    float s1 = sacc[mm][c][1] * inv64; s1 *= s1; if (kc + 1 > qr0) s1 = 0.f;
                    float s2 = sacc[mm][c][2] * inv64; s2 *= s2; if (kc > qr1)     s2 = 0.f;
                    float s3 = sacc[mm][c][3] * inv64; s3 *= s3; if (kc + 1 > qr1) s3 = 0.f;
                    float af[4];
                    af[0] = ftf(s0);
                    af[1] = ftf(s2);
                    af[2] = ftf(s1);
                    af[3] = ftf(s3);
#pragma unroll
                    for (int dn = 0; dn < 8; dn++) {
                        float bfr[2];
                        if (kh == 0) { bfr[0] = vb[dn].x; bfr[1] = vb[dn].y; }
                        else         { bfr[0] = vb[dn].z; bfr[1] = vb[dn].w; }
                        mma8(zacc[mm][dn], af, bfr);
                    }
                }
            }
        }
    }

    // ---- write Z ----
#pragma unroll
    for (int mm = 0; mm < 2; mm++) {
        int qr0 = qbase + mm * 16 + g;
        int qr1 = qr0 + 8;
#pragma unroll
        for (int dn = 0; dn < 8; dn++) {
            int col = dn * 8 + 2 * t;
            *(float2*)&Z[base + (size_t)qr0 * D_MODEL + col] =
                make_float2(zacc[mm][dn][0], zacc[mm][dn][1]);
            *(float2*)&Z[base + (size_t)qr1 * D_MODEL + col] =
                make_float2(zacc[mm][dn][2], zacc[mm][dn][3]);
        }
    }
}

// ---------------- launch ----------------
extern "C" void kernel_launch(void* const* d_in, const int* in_sizes, int n_in,
                              void* d_out, int out_size)
{
    const float* x  = (const float*)d_in[0];
    const float* Wq = (const float*)d_in[1];
    const float* bq = (const float*)d_in[2];
    const float* Wk = (const float*)d_in[3];
    const float* bk = (const float*)d_in[4];
    const float* Wv = (const float*)d_in[5];
    const float* bv = (const float*)d_in[6];
    const float* Wo = (const float*)d_in[7];
    const float* nw = (const float*)d_in[8];
    float* out = (float*)d_out;

    float *q, *k, *v, *z;
    cudaGetSymbolAddress((void**)&q, g_q);
    cudaGetSymbolAddress((void**)&k, g_k);
    cudaGetSymbolAddress((void**)&v, g_v);
    cudaGetSymbolAddress((void**)&z, g_z);

    cudaFuncSetAttribute(attn_tc_kernel, cudaFuncAttributeMaxDynamicSharedMemorySize, ATTN_SMEM);

    rope_cache_kernel<<<64, 1024>>>();

    // QKV projections: one launch, 3 jobs; q/k get fused rmsnorm+rope epilogue
    GemmJobs jq;
    jq.W[0] = Wq; jq.W[1] = Wk; jq.W[2] = Wv;
    jq.bias[0] = bq; jq.bias[1] = bk; jq.bias[2] = bv;
    jq.res[0] = nullptr; jq.res[1] = nullptr; jq.res[2] = nullptr;
    jq.out[0] = q; jq.out[1] = k; jq.out[2] = v;
    jq.norm[0] = 1; jq.norm[1] = 1; jq.norm[2] = 0;
    gemm_tc_kernel<<<dim3(D_MODEL / 128, MTOT / 128, 3), 256>>>(x, jq, nw, MTOT, D_MODEL, D_MODEL);

    attn_tc_kernel<<<dim3(16, 32), 128, ATTN_SMEM>>>(q, k, v, z);

    GemmJobs jo;
    jo.W[0] = Wo; jo.W[1] = nullptr; jo.W[2] = nullptr;
    jo.bias[0] = nullptr; jo.bias[1] = nullptr; jo.bias[2] = nullptr;
    jo.res[0] = x; jo.res[1] = nullptr; jo.res[2] = nullptr;
    jo.out[0] = out; jo.out[1] = nullptr; jo.out[2] = nullptr;
    jo.norm[0] = 0; jo.norm[1] = 0; jo.norm[2] = 0;
    gemm_tc_kernel<<<dim3(D_MODEL / 128, MTOT / 128, 1), 256>>>(z, jo, nw, MTOT, D_MODEL, D_MODEL);
}

// round 11
// speedup vs baseline: 1.1847x; 1.1847x over previous
#include <cuda_runtime.h>
#include <cuda_fp16.h>
#include <math.h>
#include <stdint.h>

#define D_MODEL 1024
#define N_HEAD  16
#define D_HEAD  64
#define N_CTX   2048
#define BATCH   2
#define MTOT    (BATCH * N_CTX)   /* 4096 rows */

// ---------------- scratch ----------------
__device__ float g_q[MTOT * D_MODEL];
__device__ float g_k[MTOT * D_MODEL];
__device__ float g_v[MTOT * D_MODEL];
__device__ float g_z[MTOT * D_MODEL];
__device__ float g_cos[N_CTX * 32];
__device__ float g_sin[N_CTX * 32];

// ---------------- helpers ----------------
__device__ __forceinline__ float ftf(float x) {
    uint32_t u;
    asm("cvt.rna.tf32.f32 %0, %1;" : "=r"(u) : "f"(x));
    return __uint_as_float(u);
}

__device__ __forceinline__ uint32_t pack2(float x, float y) {
    __half2 h = __floats2half2_rn(x, y);
    return *(uint32_t*)&h;
}

// tf32 m16n8k8 (attention)
__device__ __forceinline__ void mma8(float c[4], const float a[4], const float b[2]) {
    asm volatile(
        "mma.sync.aligned.m16n8k8.row.col.f32.tf32.tf32.f32 "
        "{%0,%1,%2,%3}, {%4,%5,%6,%7}, {%8,%9}, {%0,%1,%2,%3};\n"
        : "+f"(c[0]), "+f"(c[1]), "+f"(c[2]), "+f"(c[3])
        : "r"(__float_as_uint(a[0])), "r"(__float_as_uint(a[1])),
          "r"(__float_as_uint(a[2])), "r"(__float_as_uint(a[3])),
          "r"(__float_as_uint(b[0])), "r"(__float_as_uint(b[1])));
}

// fp16 m16n8k16 (projections)
__device__ __forceinline__ void mma16(float c[4], const uint32_t* a, const uint32_t* b) {
    asm volatile(
        "mma.sync.aligned.m16n8k16.row.col.f32.f16.f16.f32 "
        "{%0,%1,%2,%3}, {%4,%5,%6,%7}, {%8,%9}, {%0,%1,%2,%3};\n"
        : "+f"(c[0]), "+f"(c[1]), "+f"(c[2]), "+f"(c[3])
        : "r"(a[0]), "r"(a[1]), "r"(a[2]), "r"(a[3]), "r"(b[0]), "r"(b[1]));
}

// ---------------- RoPE table ----------------
__global__ void rope_cache_kernel() {
    int i = blockIdx.x * blockDim.x + threadIdx.x;
    int t = i >> 5;
    int j = i & 31;
    float invf = (float)pow(10000.0, -(double)j / 32.0);
    double ang = (double)t * (double)invf;
    double sv, cv;
    sincos(ang, &sv, &cv);
    g_cos[i] = (float)cv;
    g_sin[i] = (float)sv;
}

// ---------------- FP16 GEMM: C = A * W^T (+bias) (+res / +norm+rope), multi-job ----------------
// Block tile 128x128, BK=32 (2 k16 steps). 8 warps 4(M)x2(N), warp tile 32x64.
// Fragment-major smem; STS.64 swizzles verified conflict-free per 16-lane phase:
//   A: bank = 16(ag&1) + 4*tp + 2*hk,  tp = t ^ (((ag>>1)&1) | (ks<<1))  -> injective
//   B: bank = 8(bg&3)  + 2*tp,         tp = t ^ ((nt&1) | (ks<<1))       -> injective
struct GemmJobs {
    const float* W[3];
    const float* bias[3];
    const float* res[3];
    float*       out[3];
    int          norm[3];   // 1 => fused rmsnorm+rope epilogue (q/k jobs)
};

__global__ __launch_bounds__(256, 2)
void gemm_fp16_kernel(const float* __restrict__ A, GemmJobs jobs,
                      const float* __restrict__ nw, int M, int N, int K)
{
    __shared__ __align__(16) uint32_t As[2048];  // [ks2][mt8][lane32][reg4] 8KB
    __shared__ __align__(16) uint32_t Bs[2048];  // [ks2][nt16][lane32][reg2] 8KB

    const int z = blockIdx.z;
    const float* W    = jobs.W[z];
    const float* bias = jobs.bias[z];
    const float* res  = jobs.res[z];
    float*       C    = jobs.out[z];
    const int    donorm = jobs.norm[z];

    const int tid = threadIdx.x;
    const int lane = tid & 31;
    const int wid = tid >> 5;
    const int wm = wid & 3, wn = wid >> 2;
    const int m0 = blockIdx.y * 128, n0 = blockIdx.x * 128;

    // A loader: rows {r, r+8}, cols aks*8..+7 of the 128x32 chunk
    const int amt = tid >> 5, ag = (tid >> 2) & 7, aks = tid & 3;
    const int aksh = aks >> 1, ahk = aks & 1;
    const int axor = ((ag >> 1) & 1) | (aksh << 1);
    const float* Ap = A + (size_t)(m0 + amt * 16 + ag) * K + aks * 8;
    // B loader: one W row, 16 cols (one full k16 step)
    const int bnt = ((tid >> 5) << 1) | (tid & 1);
    const int bg = (tid >> 2) & 7;
    const int bks = (tid >> 1) & 1;
    const int bxr = (tid & 1) | (bks << 1);
    const float* Wp = W + (size_t)(n0 + bnt * 8 + bg) * K + bks * 16;

    float acc[2][8][4];
#pragma unroll
    for (int mi = 0; mi < 2; mi++)
#pragma unroll
        for (int ni = 0; ni < 8; ni++)
#pragma unroll
            for (int e = 0; e < 4; e++) acc[mi][ni][e] = 0.f;

    for (int kt = 0; kt < K; kt += 32) {
        float alo[8], ahi[8], wr[16];
        {
            float4 v0 = *(const float4*)(Ap + kt);
            float4 v1 = *(const float4*)(Ap + kt + 4);
            float4 v2 = *(const float4*)(Ap + kt + (size_t)8 * K);
            float4 v3 = *(const float4*)(Ap + kt + (size_t)8 * K + 4);
            alo[0]=v0.x;alo[1]=v0.y;alo[2]=v0.z;alo[3]=v0.w;
            alo[4]=v1.x;alo[5]=v1.y;alo[6]=v1.z;alo[7]=v1.w;
            ahi[0]=v2.x;ahi[1]=v2.y;ahi[2]=v2.z;ahi[3]=v2.w;
            ahi[4]=v3.x;ahi[5]=v3.y;ahi[6]=v3.z;ahi[7]=v3.w;
            float4 u0 = *(const float4*)(Wp + kt);
            float4 u1 = *(const float4*)(Wp + kt + 4);
            float4 u2 = *(const float4*)(Wp + kt + 8);
            float4 u3 = *(const float4*)(Wp + kt + 12);
            wr[0]=u0.x;wr[1]=u0.y;wr[2]=u0.z;wr[3]=u0.w;
            wr[4]=u1.x;wr[5]=u1.y;wr[6]=u1.z;wr[7]=u1.w;
            wr[8]=u2.x;wr[9]=u2.y;wr[10]=u2.z;wr[11]=u2.w;
            wr[12]=u3.x;wr[13]=u3.y;wr[14]=u3.z;wr[15]=u3.w;
        }
        __syncthreads();
#pragma unroll
        for (int t = 0; t < 4; t++) {
            int aslot = (aksh * 8 + amt) * 32 + 4 * ag + (t ^ axor);
            *(uint2*)&As[aslot * 4 + 2 * ahk] =
                make_uint2(pack2(alo[2 * t], alo[2 * t + 1]),
                           pack2(ahi[2 * t], ahi[2 * t + 1]));
            int bslot = (bks * 16 + bnt) * 32 + 4 * bg + (t ^ bxr);
            *(uint2*)&Bs[bslot * 2] =
                make_uint2(pack2(wr[2 * t], wr[2 * t + 1]),
                           pack2(wr[2 * t + 8], wr[2 * t + 9]));
        }
        __syncthreads();
#pragma unroll
        for (int ks = 0; ks < 2; ks++) {
            uint2 bb[8];
#pragma unroll
            for (int ni = 0; ni < 8; ni++) {
                int nt = wn * 8 + ni;
                int x = (nt & 1) | (ks << 1);
                int s = (ks * 16 + nt) * 32 + (lane & 28) + ((lane & 3) ^ x);
                bb[ni] = *(const uint2*)&Bs[s * 2];
            }
            int xa = ((lane >> 3) & 1) | (ks << 1);
            uint4 aa[2];
#pragma unroll
            for (int mi = 0; mi < 2; mi++) {
                int s = (ks * 8 + wm * 2 + mi) * 32 + (lane & 28) + ((lane & 3) ^ xa);
                aa[mi] = *(const uint4*)&As[s * 4];
            }
#pragma unroll
            for (int mi = 0; mi < 2; mi++)
#pragma unroll
                for (int ni = 0; ni < 8; ni++)
                    mma16(acc[mi][ni], (const uint32_t*)&aa[mi], (const uint32_t*)&bb[ni]);
        }
    }

    const int g = lane >> 2, t = lane & 3;
    if (donorm) {
        // warp's 64 cols = one head; rmsnorm over t-quad + rope, fused
#pragma unroll
        for (int mi = 0; mi < 2; mi++) {
#pragma unroll
            for (int h = 0; h < 2; h++) {
                int m = m0 + wm * 32 + mi * 16 + h * 8 + g;
                int s = m & (N_CTX - 1);
                float v0[8], v1[8];
                float ss = 0.f;
#pragma unroll
                for (int ni = 0; ni < 8; ni++) {
                    int n = n0 + wn * 64 + ni * 8 + 2 * t;
                    float e0 = acc[mi][ni][h * 2 + 0] + bias[n];
                    float e1 = acc[mi][ni][h * 2 + 1] + bias[n + 1];
                    v0[ni] = e0; v1[ni] = e1;
                    ss = fmaf(e0, e0, fmaf(e1, e1, ss));
                }
                ss += __shfl_xor_sync(0xffffffffu, ss, 1);
                ss += __shfl_xor_sync(0xffffffffu, ss, 2);
                float r = rsqrtf(ss * (1.0f / 64.0f) + 1.1920929e-07f);
#pragma unroll
                for (int ni = 0; ni < 8; ni++) {
                    int d = ni * 8 + 2 * t;
                    float y0 = v0[ni] * r * nw[d];
                    float y1 = v1[ni] * r * nw[d + 1];
                    int j0 = d & 31, j1 = (d + 1) & 31;
                    float o0 = y0 * g_cos[s * 32 + j0] - y1 * g_sin[s * 32 + j0];
                    float o1 = y1 * g_cos[s * 32 + j1] + y0 * g_sin[s * 32 + j1];
                    int n = n0 + wn * 64 + d;
                    *(float2*)&C[(size_t)m * N + n] = make_float2(o0, o1);
                }
            }
        }
    } else {
#pragma unroll
        for (int mi = 0; mi < 2; mi++) {
#pragma unroll
            for (int h = 0; h < 2; h++) {
                int m = m0 + wm * 32 + mi * 16 + h * 8 + g;
#pragma unroll
                for (int ni = 0; ni < 8; ni++) {
                    int n = n0 + wn * 64 + ni * 8 + 2 * t;
                    float2 v = make_float2(acc[mi][ni][h * 2 + 0], acc[mi][ni][h * 2 + 1]);
                    if (bias) { v.x += bias[n]; v.y += bias[n + 1]; }
                    if (res) {
                        float2 r = *(const float2*)&res[(size_t)m * N + n];
                        v.x += r.x; v.y += r.y;
                    }
                    *(float2*)&C[(size_t)m * N + n] = v;
                }
            }
        }
    }
}

// ---------------- fused quadratic causal attention, TF32 mma (R8 proven) ----------------
// CTA: 128 threads (4 warps), q-tile 128; warp owns 32 q-rows x full 64-k.
// Shuffle-free P via V row permutation l(r)=(r&1)*4+(r>>1).
#define ATTN_SMEM (16384 * 4)   /* 64 KB: Qs 32KB | Ks 16KB | Vs 16KB */

__global__ __launch_bounds__(128)
void attn_tc_kernel(const float* __restrict__ Q, const float* __restrict__ Kg,
                    const float* __restrict__ V, float* __restrict__ Z)
{
    extern __shared__ float sm[];
    float4* Qs4 = (float4*)sm;        // [ks8][mt8][lane32] float4 frags
    float*  KsF = sm + 8192;          // frag-major K
    float*  VsF = sm + 12288;         // frag-major V (k-permuted)

    const int tid = threadIdx.x;
    const int lane = tid & 31;
    const int wp = tid >> 5;
    const int g = lane >> 2, t = lane & 3;
    const int bh = blockIdx.y;
    const int b = bh >> 4, h = bh & 15;
    const int jt = (int)gridDim.x - 1 - (int)blockIdx.x;   // big tiles first
    const size_t base = (size_t)(b * N_CTX) * D_MODEL + h * 64;
    const int nkt = 2 * jt + 2;

    // ---- Q tile (128 x 64) -> fragment-major smem, once ----
    {
        const int r0 = tid >> 4, c4 = tid & 15;
        const int qks = c4 >> 1, th = c4 & 1;
        const int kx = qks & 3;
#pragma unroll
        for (int j = 0; j < 16; j++) {
            int r = 8 * j + r0;
            int mt = r >> 4, gg = r & 15;
            int comp = (gg >> 3) + 2 * th;
            int gq = gg & 7;
            float4 qv = *(const float4*)&Q[base + (size_t)(jt * 128 + r) * D_MODEL + c4 * 4];
            float vals[4] = {qv.x, qv.y, qv.z, qv.w};
            float* dst = (float*)Qs4 + ((qks * 8 + mt) * 32) * 4 + comp;
#pragma unroll
            for (int i = 0; i < 4; i++)
                dst[(4 * gq + (i ^ kx)) * 4] = ftf(vals[i]);
        }
    }

    float zacc[2][8][4];
#pragma unroll
    for (int mm = 0; mm < 2; mm++)
#pragma unroll
        for (int i = 0; i < 8; i++)
#pragma unroll
            for (int j = 0; j < 4; j++) zacc[mm][i][j] = 0.f;

    const int krow0 = tid >> 4, kcol4 = tid & 15;
    const int kksp = kcol4 >> 2, kcomp = kcol4 & 3;
    const int vrow = tid & 63, vh = tid >> 6;
    const int vcp = vrow >> 4;
    const int vrr = vrow & 7;
    const int vkh = (vrow >> 3) & 1;
    const int vtt = vrr >> 1;
    const int vcomp = (vrr & 1) | (vkh << 1);
    const int vg0 = vh * 4;
    const int vsw = vtt ^ (vcp & 3);

    const float* kbase = Kg + base;
    const float* vbase = V + base;

    const float inv64 = 1.0f / 64.0f;
    const int qbase = jt * 128 + wp * 32;

    for (int kt = 0; kt < nkt; ++kt) {
        const int ktb = kt * 64;
        __syncthreads();
#pragma unroll
        for (int j = 0; j < 8; j++) {
            float4 kv = *(const float4*)&kbase[(size_t)(ktb + krow0 + 8 * j) * D_MODEL + kcol4 * 4];
            int bb = (kksp * 8 + j) * 32 + krow0 * 4;
            KsF[(bb + (0 ^ kksp)) * 4 + kcomp] = ftf(kv.x);
            KsF[(bb + (1 ^ kksp)) * 4 + kcomp] = ftf(kv.y);
            KsF[(bb + (2 ^ kksp)) * 4 + kcomp] = ftf(kv.z);
            KsF[(bb + (3 ^ kksp)) * 4 + kcomp] = ftf(kv.w);
        }
#pragma unroll
        for (int j = 0; j < 8; j++) {
            float4 vv = *(const float4*)&vbase[(size_t)(ktb + vrow) * D_MODEL + (vh + 2 * j) * 4];
            int bb = (vcp * 8 + j) * 32 + vg0 * 4 + vsw;
            VsF[(bb + 0)  * 4 + vcomp] = ftf(vv.x);
            VsF[(bb + 4)  * 4 + vcomp] = ftf(vv.y);
            VsF[(bb + 8)  * 4 + vcomp] = ftf(vv.z);
            VsF[(bb + 12) * 4 + vcomp] = ftf(vv.w);
        }
        __syncthreads();

        const float4* KsP = (const float4*)KsF;
        const float4* VsP = (const float4*)VsF;

        float sacc[2][8][4];
#pragma unroll
        for (int mm = 0; mm < 2; mm++)
#pragma unroll
            for (int i = 0; i < 8; i++)
#pragma unroll
                for (int j = 0; j < 4; j++) sacc[mm][i][j] = 0.f;

#pragma unroll
        for (int ksp = 0; ksp < 4; ksp++) {
            int slot = (lane & 28) | ((lane & 3) ^ ksp);
            float4 kb[8];
#pragma unroll
            for (int nt = 0; nt < 8; nt++)
                kb[nt] = KsP[(ksp * 8 + nt) * 32 + slot];
#pragma unroll
            for (int kh = 0; kh < 2; kh++) {
                int ks = ksp * 2 + kh;
                int qslot = (lane & 28) | ((lane & 3) ^ (ks & 3));
                float4 qa0 = Qs4[(ks * 8 + wp * 2 + 0) * 32 + qslot];
                float4 qa1 = Qs4[(ks * 8 + wp * 2 + 1) * 32 + qslot];
                float a0[4] = {qa0.x, qa0.y, qa0.z, qa0.w};
                float a1[4] = {qa1.x, qa1.y, qa1.z, qa1.w};
#pragma unroll
                for (int nt = 0; nt < 8; nt++) {
                    float bfr[2];
                    if (kh == 0) { bfr[0] = kb[nt].x; bfr[1] = kb[nt].y; }
                    else         { bfr[0] = kb[nt].z; bfr[1] = kb[nt].w; }
                    mma8(sacc[0][nt], a0, bfr);
                    mma8(sacc[1][nt], a1, bfr);
                }
            }
        }

#pragma unroll
        for (int cp = 0; cp < 4; cp++) {
            int vslot = (lane & 28) | ((lane & 3) ^ (cp & 3));
            float4 vb[8];
#pragma unroll
            for (int dn = 0; dn < 8; dn++)
                vb[dn] = VsP[(cp * 8 + dn) * 32 + vslot];
#pragma unroll
            for (int kh = 0; kh < 2; kh++) {
                int c = cp * 2 + kh;
                int kc = ktb + c * 8 + 2 * t;
#pragma unroll
                for (int mm = 0; mm < 2; mm++) {
                    int qr0 = qbase + mm * 16 + g;
                    int qr1 = qr0 + 8;
                    float s0 = sacc[mm][c][0] * inv64; s0 *= s0; if (kc > qr0)     s0 = 0.f;
                    float s1 = sacc[mm][c][1] * inv64; s1 *= s1; if (kc + 1 > qr0) s1 = 0.f;
                    float s2 = sacc[mm][c][2] * inv64; s2 *= s2; if (kc > qr1)     s2 = 0.f;
                    float s3 = sacc[mm][c][3] * inv64; s3 *= s3; if (kc + 1 > qr1) s3 = 0.f;
                    float af[4];
                    af[0] = ftf(s0);
                    af[1] = ftf(s2);
                    af[2] = ftf(s1);
                    af[3] = ftf(s3);
#pragma unroll
                    for (int dn = 0; dn < 8; dn++) {
                        float bfr[2];
                        if (kh == 0) { bfr[0] = vb[dn].x; bfr[1] = vb[dn].y; }
                        else         { bfr[0] = vb[dn].z; bfr[1] = vb[dn].w; }
                        mma8(zacc[mm][dn], af, bfr);
                    }
                }
            }
        }
    }

#pragma unroll
    for (int mm = 0; mm < 2; mm++) {
        int qr0 = qbase + mm * 16 + g;
        int qr1 = qr0 + 8;
#pragma unroll
        for (int dn = 0; dn < 8; dn++) {
            int col = dn * 8 + 2 * t;
            *(float2*)&Z[base + (size_t)qr0 * D_MODEL + col] =
                make_float2(zacc[mm][dn][0], zacc[mm][dn][1]);
            *(float2*)&Z[base + (size_t)qr1 * D_MODEL + col] =
                make_float2(zacc[mm][dn][2], zacc[mm][dn][3]);
        }
    }
}

// ---------------- launch ----------------
extern "C" void kernel_launch(void* const* d_in, const int* in_sizes, int n_in,
                              void* d_out, int out_size)
{
    const float* x  = (const float*)d_in[0];
    const float* Wq = (const float*)d_in[1];
    const float* bq = (const float*)d_in[2];
    const float* Wk = (const float*)d_in[3];
    const float* bk = (const float*)d_in[4];
    const float* Wv = (const float*)d_in[5];
    const float* bv = (const float*)d_in[6];
    const float* Wo = (const float*)d_in[7];
    const float* nw = (const float*)d_in[8];
    float* out = (float*)d_out;

    float *q, *k, *v, *z;
    cudaGetSymbolAddress((void**)&q, g_q);
    cudaGetSymbolAddress((void**)&k, g_k);
    cudaGetSymbolAddress((void**)&v, g_v);
    cudaGetSymbolAddress((void**)&z, g_z);

    cudaFuncSetAttribute(attn_tc_kernel, cudaFuncAttributeMaxDynamicSharedMemorySize, ATTN_SMEM);

    rope_cache_kernel<<<64, 1024>>>();

    // QKV projections: one launch, 3 jobs; q/k get fused rmsnorm+rope epilogue
    GemmJobs jq;
    jq.W[0] = Wq; jq.W[1] = Wk; jq.W[2] = Wv;
    jq.bias[0] = bq; jq.bias[1] = bk; jq.bias[2] = bv;
    jq.res[0] = nullptr; jq.res[1] = nullptr; jq.res[2] = nullptr;
    jq.out[0] = q; jq.out[1] = k; jq.out[2] = v;
    jq.norm[0] = 1; jq.norm[1] = 1; jq.norm[2] = 0;
    gemm_fp16_kernel<<<dim3(D_MODEL / 128, MTOT / 128, 3), 256>>>(x, jq, nw, MTOT, D_MODEL, D_MODEL);

    attn_tc_kernel<<<dim3(16, 32), 128, ATTN_SMEM>>>(q, k, v, z);

    // output projection + residual
    GemmJobs jo;
    jo.W[0] = Wo; jo.W[1] = nullptr; jo.W[2] = nullptr;
    jo.bias[0] = nullptr; jo.bias[1] = nullptr; jo.bias[2] = nullptr;
    jo.res[0] = x; jo.res[1] = nullptr; jo.res[2] = nullptr;
    jo.out[0] = out; jo.out[1] = nullptr; jo.out[2] = nullptr;
    jo.norm[0] = 0; jo.norm[1] = 0; jo.norm[2] = 0;
    gemm_fp16_kernel<<<dim3(D_MODEL / 128, MTOT / 128, 1), 256>>>(z, jo, nw, MTOT, D_MODEL, D_MODEL);
}

// round 12
// speedup vs baseline: 1.3126x; 1.1080x over previous
#include <cuda_runtime.h>
#include <cuda_fp16.h>
#include <math.h>
#include <stdint.h>

#define D_MODEL 1024
#define N_HEAD  16
#define D_HEAD  64
#define N_CTX   2048
#define BATCH   2
#define MTOT    (BATCH * N_CTX)   /* 4096 rows */

// ---------------- scratch ----------------
__device__ float g_q[MTOT * D_MODEL];
__device__ float g_k[MTOT * D_MODEL];
__device__ float g_v[MTOT * D_MODEL];
__device__ float g_z[MTOT * D_MODEL];
__device__ float g_cos[N_CTX * 32];
__device__ float g_sin[N_CTX * 32];

// ---------------- helpers ----------------
__device__ __forceinline__ uint32_t pack2(float x, float y) {
    __half2 h = __floats2half2_rn(x, y);
    return *(uint32_t*)&h;
}

// fp16 m16n8k16
__device__ __forceinline__ void mma16(float c[4], const uint32_t* a, const uint32_t* b) {
    asm volatile(
        "mma.sync.aligned.m16n8k16.row.col.f32.f16.f16.f32 "
        "{%0,%1,%2,%3}, {%4,%5,%6,%7}, {%8,%9}, {%0,%1,%2,%3};\n"
        : "+f"(c[0]), "+f"(c[1]), "+f"(c[2]), "+f"(c[3])
        : "r"(a[0]), "r"(a[1]), "r"(a[2]), "r"(a[3]), "r"(b[0]), "r"(b[1]));
}

// ---------------- RoPE table ----------------
__global__ void rope_cache_kernel() {
    int i = blockIdx.x * blockDim.x + threadIdx.x;
    int t = i >> 5;
    int j = i & 31;
    float invf = (float)pow(10000.0, -(double)j / 32.0);
    double ang = (double)t * (double)invf;
    double sv, cv;
    sincos(ang, &sv, &cv);
    g_cos[i] = (float)cv;
    g_sin[i] = (float)sv;
}

// ---------------- FP16 GEMM: C = A * W^T (+bias) (+res / +norm+rope), multi-job ----------------
struct GemmJobs {
    const float* W[3];
    const float* bias[3];
    const float* res[3];
    float*       out[3];
    int          norm[3];   // 1 => fused rmsnorm+rope epilogue (q/k jobs)
};

__global__ __launch_bounds__(256, 2)
void gemm_fp16_kernel(const float* __restrict__ A, GemmJobs jobs,
                      const float* __restrict__ nw, int M, int N, int K)
{
    __shared__ __align__(16) uint32_t As[2048];  // [ks2][mt8][lane32][reg4] 8KB
    __shared__ __align__(16) uint32_t Bs[2048];  // [ks2][nt16][lane32][reg2] 8KB

    const int z = blockIdx.z;
    const float* W    = jobs.W[z];
    const float* bias = jobs.bias[z];
    const float* res  = jobs.res[z];
    float*       C    = jobs.out[z];
    const int    donorm = jobs.norm[z];

    const int tid = threadIdx.x;
    const int lane = tid & 31;
    const int wid = tid >> 5;
    const int wm = wid & 3, wn = wid >> 2;
    const int m0 = blockIdx.y * 128, n0 = blockIdx.x * 128;

    const int amt = tid >> 5, ag = (tid >> 2) & 7, aks = tid & 3;
    const int aksh = aks >> 1, ahk = aks & 1;
    const int axor = ((ag >> 1) & 1) | (aksh << 1);
    const float* Ap = A + (size_t)(m0 + amt * 16 + ag) * K + aks * 8;
    const int bnt = ((tid >> 5) << 1) | (tid & 1);
    const int bg = (tid >> 2) & 7;
    const int bks = (tid >> 1) & 1;
    const int bxr = (tid & 1) | (bks << 1);
    const float* Wp = W + (size_t)(n0 + bnt * 8 + bg) * K + bks * 16;

    float acc[2][8][4];
#pragma unroll
    for (int mi = 0; mi < 2; mi++)
#pragma unroll
        for (int ni = 0; ni < 8; ni++)
#pragma unroll
            for (int e = 0; e < 4; e++) acc[mi][ni][e] = 0.f;

    for (int kt = 0; kt < K; kt += 32) {
        float alo[8], ahi[8], wr[16];
        {
            float4 v0 = *(const float4*)(Ap + kt);
            float4 v1 = *(const float4*)(Ap + kt + 4);
            float4 v2 = *(const float4*)(Ap + kt + (size_t)8 * K);
            float4 v3 = *(const float4*)(Ap + kt + (size_t)8 * K + 4);
            alo[0]=v0.x;alo[1]=v0.y;alo[2]=v0.z;alo[3]=v0.w;
            alo[4]=v1.x;alo[5]=v1.y;alo[6]=v1.z;alo[7]=v1.w;
            ahi[0]=v2.x;ahi[1]=v2.y;ahi[2]=v2.z;ahi[3]=v2.w;
            ahi[4]=v3.x;ahi[5]=v3.y;ahi[6]=v3.z;ahi[7]=v3.w;
            float4 u0 = *(const float4*)(Wp + kt);
            float4 u1 = *(const float4*)(Wp + kt + 4);
            float4 u2 = *(const float4*)(Wp + kt + 8);
            float4 u3 = *(const float4*)(Wp + kt + 12);
            wr[0]=u0.x;wr[1]=u0.y;wr[2]=u0.z;wr[3]=u0.w;
            wr[4]=u1.x;wr[5]=u1.y;wr[6]=u1.z;wr[7]=u1.w;
            wr[8]=u2.x;wr[9]=u2.y;wr[10]=u2.z;wr[11]=u2.w;
            wr[12]=u3.x;wr[13]=u3.y;wr[14]=u3.z;wr[15]=u3.w;
        }
        __syncthreads();
#pragma unroll
        for (int t = 0; t < 4; t++) {
            int aslot = (aksh * 8 + amt) * 32 + 4 * ag + (t ^ axor);
            *(uint2*)&As[aslot * 4 + 2 * ahk] =
                make_uint2(pack2(alo[2 * t], alo[2 * t + 1]),
                           pack2(ahi[2 * t], ahi[2 * t + 1]));
            int bslot = (bks * 16 + bnt) * 32 + 4 * bg + (t ^ bxr);
            *(uint2*)&Bs[bslot * 2] =
                make_uint2(pack2(wr[2 * t], wr[2 * t + 1]),
                           pack2(wr[2 * t + 8], wr[2 * t + 9]));
        }
        __syncthreads();
#pragma unroll
        for (int ks = 0; ks < 2; ks++) {
            uint2 bb[8];
#pragma unroll
            for (int ni = 0; ni < 8; ni++) {
                int nt = wn * 8 + ni;
                int x = (nt & 1) | (ks << 1);
                int s = (ks * 16 + nt) * 32 + (lane & 28) + ((lane & 3) ^ x);
                bb[ni] = *(const uint2*)&Bs[s * 2];
            }
            int xa = ((lane >> 3) & 1) | (ks << 1);
            uint4 aa[2];
#pragma unroll
            for (int mi = 0; mi < 2; mi++) {
                int s = (ks * 8 + wm * 2 + mi) * 32 + (lane & 28) + ((lane & 3) ^ xa);
                aa[mi] = *(const uint4*)&As[s * 4];
            }
#pragma unroll
            for (int mi = 0; mi < 2; mi++)
#pragma unroll
                for (int ni = 0; ni < 8; ni++)
                    mma16(acc[mi][ni], (const uint32_t*)&aa[mi], (const uint32_t*)&bb[ni]);
        }
    }

    const int g = lane >> 2, t = lane & 3;
    if (donorm) {
#pragma unroll
        for (int mi = 0; mi < 2; mi++) {
#pragma unroll
            for (int h = 0; h < 2; h++) {
                int m = m0 + wm * 32 + mi * 16 + h * 8 + g;
                int s = m & (N_CTX - 1);
                float v0[8], v1[8];
                float ss = 0.f;
#pragma unroll
                for (int ni = 0; ni < 8; ni++) {
                    int n = n0 + wn * 64 + ni * 8 + 2 * t;
                    float e0 = acc[mi][ni][h * 2 + 0] + bias[n];
                    float e1 = acc[mi][ni][h * 2 + 1] + bias[n + 1];
                    v0[ni] = e0; v1[ni] = e1;
                    ss = fmaf(e0, e0, fmaf(e1, e1, ss));
                }
                ss += __shfl_xor_sync(0xffffffffu, ss, 1);
                ss += __shfl_xor_sync(0xffffffffu, ss, 2);
                float r = rsqrtf(ss * (1.0f / 64.0f) + 1.1920929e-07f);
#pragma unroll
                for (int ni = 0; ni < 8; ni++) {
                    int d = ni * 8 + 2 * t;
                    float y0 = v0[ni] * r * nw[d];
                    float y1 = v1[ni] * r * nw[d + 1];
                    int j0 = d & 31, j1 = (d + 1) & 31;
                    float o0 = y0 * g_cos[s * 32 + j0] - y1 * g_sin[s * 32 + j0];
                    float o1 = y1 * g_cos[s * 32 + j1] + y0 * g_sin[s * 32 + j1];
                    int n = n0 + wn * 64 + d;
                    *(float2*)&C[(size_t)m * N + n] = make_float2(o0, o1);
                }
            }
        }
    } else {
#pragma unroll
        for (int mi = 0; mi < 2; mi++) {
#pragma unroll
            for (int h = 0; h < 2; h++) {
                int m = m0 + wm * 32 + mi * 16 + h * 8 + g;
#pragma unroll
                for (int ni = 0; ni < 8; ni++) {
                    int n = n0 + wn * 64 + ni * 8 + 2 * t;
                    float2 v = make_float2(acc[mi][ni][h * 2 + 0], acc[mi][ni][h * 2 + 1]);
                    if (bias) { v.x += bias[n]; v.y += bias[n + 1]; }
                    if (res) {
                        float2 r = *(const float2*)&res[(size_t)m * N + n];
                        v.x += r.x; v.y += r.y;
                    }
                    *(float2*)&C[(size_t)m * N + n] = v;
                }
            }
        }
    }
}

// ---------------- fused quadratic causal attention, FP16 mma ----------------
// CTA: 128 threads (4 warps), q-tile 128; warp owns 32 q-rows x full 64-k.
// Q as A-frags (16KB), K as B-frags (8KB), V as B-frags packed along key dim
// with stride-36 padding (9KB). S C-frag packs DIRECTLY into P A-frag (no shfl).
#define QH_OFF 0
#define KH_OFF 16384
#define VH_OFF (16384 + 8192)
#define ATTN_SMEM (16384 + 8192 + 9216)   /* 33792 B */

__global__ __launch_bounds__(128)
void attn_fp16_kernel(const float* __restrict__ Q, const float* __restrict__ Kg,
                      const float* __restrict__ V, float* __restrict__ Z)
{
    extern __shared__ char smc[];
    uint4* Qh = (uint4*)(smc + QH_OFF);     // [ks4][mt8][lane32]
    uint2* Kh = (uint2*)(smc + KH_OFF);     // [ks4][nt8][lane32]
    uint2* Vh = (uint2*)(smc + VH_OFF);     // [cp4][dn8][36 padded slots]

    const int tid = threadIdx.x;
    const int lane = tid & 31;
    const int wp = tid >> 5;                 // warp 0..3
    const int g = lane >> 2, t = lane & 3;
    const int bh = blockIdx.y;
    const int b = bh >> 4, h = bh & 15;
    const int jt = (int)gridDim.x - 1 - (int)blockIdx.x;   // big tiles first
    const size_t base = (size_t)(b * N_CTX) * D_MODEL + h * 64;
    const int nkt = 2 * jt + 2;

    // ---- Q tile (128 x 64) -> A-frag smem, once ----
    {
        const int qmt = tid >> 4;           // 0..7
        const int qg = (tid >> 1) & 7;      // 0..7
        const int dh = tid & 1;             // 0..1
        const float* qp0 = Q + base + (size_t)(jt * 128 + qmt * 16 + qg) * D_MODEL + dh * 32;
        const float* qp1 = qp0 + (size_t)8 * D_MODEL;
#pragma unroll
        for (int kl = 0; kl < 2; kl++) {
            float v0[16], v1[16];
#pragma unroll
            for (int i = 0; i < 4; i++) {
                *(float4*)&v0[4 * i] = *(const float4*)(qp0 + kl * 16 + 4 * i);
                *(float4*)&v1[4 * i] = *(const float4*)(qp1 + kl * 16 + 4 * i);
            }
            int ks = dh * 2 + kl;
            int x = ((qg >> 1) & 1) | ((ks >> 1) << 1);
#pragma unroll
            for (int tt = 0; tt < 4; tt++) {
                Qh[(ks * 8 + qmt) * 32 + qg * 4 + (tt ^ x)] =
                    make_uint4(pack2(v0[2 * tt], v0[2 * tt + 1]),
                               pack2(v1[2 * tt], v1[2 * tt + 1]),
                               pack2(v0[2 * tt + 8], v0[2 * tt + 9]),
                               pack2(v1[2 * tt + 8], v1[2 * tt + 9]));
            }
        }
    }

    float zacc[2][8][4];
#pragma unroll
    for (int mm = 0; mm < 2; mm++)
#pragma unroll
        for (int i = 0; i < 8; i++)
#pragma unroll
            for (int j = 0; j < 4; j++) zacc[mm][i][j] = 0.f;

    // K loader: key row kr, d half ksh (32 d)
    const int kr = tid & 63, ksh = tid >> 6;
    const int knt = kr >> 3, kg = kr & 7;
    const int kx = (kg >> 2) | ((knt & 1) << 1);
    // V loader: cp group, key pair vt (+8), d block vdq
    const int vcp = tid >> 5;
    const int vdq = (tid >> 2) & 7;
    const int vt = tid & 3;

    const float* kbase = Kg + base;
    const float* vbase = V + base;

    const float inv64 = 1.0f / 64.0f;
    const int qbase = jt * 128 + wp * 32;

    for (int kt = 0; kt < nkt; ++kt) {
        const int ktb = kt * 64;
        __syncthreads();   // prev iteration consumers done (covers Q store at kt=0)

        // ---- K tile -> B-frag smem ----
        {
            const float* kp = kbase + (size_t)(ktb + kr) * D_MODEL + ksh * 32;
            float v[32];
#pragma unroll
            for (int i = 0; i < 8; i++)
                *(float4*)&v[4 * i] = *(const float4*)(kp + 4 * i);
#pragma unroll
            for (int kl = 0; kl < 2; kl++) {
                int ks = ksh * 2 + kl;
#pragma unroll
                for (int tt = 0; tt < 4; tt++) {
                    Kh[(ks * 8 + knt) * 32 + kg * 4 + (tt ^ kx)] =
                        make_uint2(pack2(v[16 * kl + 2 * tt], v[16 * kl + 2 * tt + 1]),
                                   pack2(v[16 * kl + 2 * tt + 8], v[16 * kl + 2 * tt + 9]));
                }
            }
        }
        // ---- V tile -> B-frag smem (keys packed in half2, stride-36 pad) ----
        {
            int ra = ktb + 16 * vcp + 2 * vt;
            const float* pa = vbase + (size_t)ra * D_MODEL + vdq * 8;
            const float* pb = pa + (size_t)1 * D_MODEL;
            const float* pc = pa + (size_t)8 * D_MODEL;
            const float* pd = pa + (size_t)9 * D_MODEL;
            float a[8], bb[8], c[8], d8[8];
            *(float4*)&a[0]  = *(const float4*)(pa);     *(float4*)&a[4]  = *(const float4*)(pa + 4);
            *(float4*)&bb[0] = *(const float4*)(pb);     *(float4*)&bb[4] = *(const float4*)(pb + 4);
            *(float4*)&c[0]  = *(const float4*)(pc);     *(float4*)&c[4]  = *(const float4*)(pc + 4);
            *(float4*)&d8[0] = *(const float4*)(pd);     *(float4*)&d8[4] = *(const float4*)(pd + 4);
#pragma unroll
            for (int i = 0; i < 8; i++) {
                Vh[(vcp * 8 + vdq) * 36 + i * 4 + vt] =
                    make_uint2(pack2(a[i], bb[i]), pack2(c[i], d8[i]));
            }
        }
        __syncthreads();

        // ---- GEMM1: S[32 x 64] per warp, 4 k16 steps over d ----
        float sacc[2][8][4];
#pragma unroll
        for (int mm = 0; mm < 2; mm++)
#pragma unroll
            for (int i = 0; i < 8; i++)
#pragma unroll
                for (int j = 0; j < 4; j++) sacc[mm][i][j] = 0.f;

#pragma unroll
        for (int ks = 0; ks < 4; ks++) {
            int qx = ((g >> 1) & 1) | ((ks >> 1) << 1);
            uint4 qa0 = Qh[(ks * 8 + wp * 2 + 0) * 32 + g * 4 + (t ^ qx)];
            uint4 qa1 = Qh[(ks * 8 + wp * 2 + 1) * 32 + g * 4 + (t ^ qx)];
#pragma unroll
            for (int nt = 0; nt < 8; nt++) {
                int xk = (g >> 2) | ((nt & 1) << 1);
                uint2 kb = Kh[(ks * 8 + nt) * 32 + g * 4 + (t ^ xk)];
                mma16(sacc[0][nt], (const uint32_t*)&qa0, (const uint32_t*)&kb);
                mma16(sacc[1][nt], (const uint32_t*)&qa1, (const uint32_t*)&kb);
            }
        }

        // ---- P = (S/64)^2 * causal -> direct A-frag pack; GEMM2 ----
#pragma unroll
        for (int cp = 0; cp < 4; cp++) {
            uint2 vb[8];
#pragma unroll
            for (int dn = 0; dn < 8; dn++)
                vb[dn] = Vh[(cp * 8 + dn) * 36 + g * 4 + t];
#pragma unroll
            for (int mm = 0; mm < 2; mm++) {
                int qr0 = qbase + mm * 16 + g;
                int qr1 = qr0 + 8;
                int c0 = 2 * cp, c1 = 2 * cp + 1;
                int kc0 = ktb + c0 * 8 + 2 * t;
                int kc1 = ktb + c1 * 8 + 2 * t;
                float p00 = sacc[mm][c0][0] * inv64; p00 *= p00; if (kc0 > qr0)     p00 = 0.f;
                float p01 = sacc[mm][c0][1] * inv64; p01 *= p01; if (kc0 + 1 > qr0) p01 = 0.f;
                float p02 = sacc[mm][c0][2] * inv64; p02 *= p02; if (kc0 > qr1)     p02 = 0.f;
                float p03 = sacc[mm][c0][3] * inv64; p03 *= p03; if (kc0 + 1 > qr1) p03 = 0.f;
                float p10 = sacc[mm][c1][0] * inv64; p10 *= p10; if (kc1 > qr0)     p10 = 0.f;
                float p11 = sacc[mm][c1][1] * inv64; p11 *= p11; if (kc1 + 1 > qr0) p11 = 0.f;
                float p12 = sacc[mm][c1][2] * inv64; p12 *= p12; if (kc1 > qr1)     p12 = 0.f;
                float p13 = sacc[mm][c1][3] * inv64; p13 *= p13; if (kc1 + 1 > qr1) p13 = 0.f;
                uint32_t af[4];
                af[0] = pack2(p00, p01);
                af[1] = pack2(p02, p03);
                af[2] = pack2(p10, p11);
                af[3] = pack2(p12, p13);
#pragma unroll
                for (int dn = 0; dn < 8; dn++)
                    mma16(zacc[mm][dn], af, (const uint32_t*)&vb[dn]);
            }
        }
    }

    // ---- write Z ----
#pragma unroll
    for (int mm = 0; mm < 2; mm++) {
        int qr0 = qbase + mm * 16 + g;
        int qr1 = qr0 + 8;
#pragma unroll
        for (int dn = 0; dn < 8; dn++) {
            int col = dn * 8 + 2 * t;
            *(float2*)&Z[base + (size_t)qr0 * D_MODEL + col] =
                make_float2(zacc[mm][dn][0], zacc[mm][dn][1]);
            *(float2*)&Z[base + (size_t)qr1 * D_MODEL + col] =
                make_float2(zacc[mm][dn][2], zacc[mm][dn][3]);
        }
    }
}

// ---------------- launch ----------------
extern "C" void kernel_launch(void* const* d_in, const int* in_sizes, int n_in,
                              void* d_out, int out_size)
{
    const float* x  = (const float*)d_in[0];
    const float* Wq = (const float*)d_in[1];
    const float* bq = (const float*)d_in[2];
    const float* Wk = (const float*)d_in[3];
    const float* bk = (const float*)d_in[4];
    const float* Wv = (const float*)d_in[5];
    const float* bv = (const float*)d_in[6];
    const float* Wo = (const float*)d_in[7];
    const float* nw = (const float*)d_in[8];
    float* out = (float*)d_out;

    float *q, *k, *v, *z;
    cudaGetSymbolAddress((void**)&q, g_q);
    cudaGetSymbolAddress((void**)&k, g_k);
    cudaGetSymbolAddress((void**)&v, g_v);
    cudaGetSymbolAddress((void**)&z, g_z);

    cudaFuncSetAttribute(attn_fp16_kernel, cudaFuncAttributeMaxDynamicSharedMemorySize, ATTN_SMEM);

    rope_cache_kernel<<<64, 1024>>>();

    // QKV projections: one launch, 3 jobs; q/k get fused rmsnorm+rope epilogue
    GemmJobs jq;
    jq.W[0] = Wq; jq.W[1] = Wk; jq.W[2] = Wv;
    jq.bias[0] = bq; jq.bias[1] = bk; jq.bias[2] = bv;
    jq.res[0] = nullptr; jq.res[1] = nullptr; jq.res[2] = nullptr;
    jq.out[0] = q; jq.out[1] = k; jq.out[2] = v;
    jq.norm[0] = 1; jq.norm[1] = 1; jq.norm[2] = 0;
    gemm_fp16_kernel<<<dim3(D_MODEL / 128, MTOT / 128, 3), 256>>>(x, jq, nw, MTOT, D_MODEL, D_MODEL);

    attn_fp16_kernel<<<dim3(16, 32), 128, ATTN_SMEM>>>(q, k, v, z);

    // output projection + residual
    GemmJobs jo;
    jo.W[0] = Wo; jo.W[1] = nullptr; jo.W[2] = nullptr;
    jo.bias[0] = nullptr; jo.bias[1] = nullptr; jo.bias[2] = nullptr;
    jo.res[0] = x; jo.res[1] = nullptr; jo.res[2] = nullptr;
    jo.out[0] = out; jo.out[1] = nullptr; jo.out[2] = nullptr;
    jo.norm[0] = 0; jo.norm[1] = 0; jo.norm[2] = 0;
    gemm_fp16_kernel<<<dim3(D_MODEL / 128, MTOT / 128, 1), 256>>>(z, jo, nw, MTOT, D_MODEL, D_MODEL);
}

// round 13
// speedup vs baseline: 1.3914x; 1.0600x over previous
#include <cuda_runtime.h>
#include <cuda_fp16.h>
#include <math.h>
#include <stdint.h>

#define D_MODEL 1024
#define N_HEAD  16
#define D_HEAD  64
#define N_CTX   2048
#define BATCH   2
#define MTOT    (BATCH * N_CTX)   /* 4096 rows */

// ---------------- scratch ----------------
__device__ float  g_q[MTOT * D_MODEL];
__device__ float  g_k[MTOT * D_MODEL];
__device__ float  g_v[MTOT * D_MODEL];
__device__ __half g_zh[MTOT * D_MODEL];
__device__ __half g_xh[MTOT * D_MODEL];
__device__ __half g_wqh[D_MODEL * D_MODEL];
__device__ __half g_wkh[D_MODEL * D_MODEL];
__device__ __half g_wvh[D_MODEL * D_MODEL];
__device__ __half g_woh[D_MODEL * D_MODEL];
__device__ float  g_cos[N_CTX * 32];
__device__ float  g_sin[N_CTX * 32];

// ---------------- helpers ----------------
__device__ __forceinline__ uint32_t pack2(float x, float y) {
    __half2 h = __floats2half2_rn(x, y);
    return *(uint32_t*)&h;
}

// fp16 m16n8k16
__device__ __forceinline__ void mma16(float c[4], const uint32_t* a, const uint32_t* b) {
    asm volatile(
        "mma.sync.aligned.m16n8k16.row.col.f32.f16.f16.f32 "
        "{%0,%1,%2,%3}, {%4,%5,%6,%7}, {%8,%9}, {%0,%1,%2,%3};\n"
        : "+f"(c[0]), "+f"(c[1]), "+f"(c[2]), "+f"(c[3])
        : "r"(a[0]), "r"(a[1]), "r"(a[2]), "r"(a[3]), "r"(b[0]), "r"(b[1]));
}

// ---------------- RoPE table ----------------
__global__ void rope_cache_kernel() {
    int i = blockIdx.x * blockDim.x + threadIdx.x;
    int t = i >> 5;
    int j = i & 31;
    float invf = (float)pow(10000.0, -(double)j / 32.0);
    double ang = (double)t * (double)invf;
    double sv, cv;
    sincos(ang, &sv, &cv);
    g_cos[i] = (float)cv;
    g_sin[i] = (float)sv;
}

// ---------------- fp32 -> fp16 conversion (x + 4 weight matrices) ----------------
struct CvtJobs {
    const float* src[5];
    __half*      dst[5];
    int          n[5];
};

__global__ __launch_bounds__(256)
void cvt_kernel(CvtJobs j) {
    int z = blockIdx.y;
    int i = (blockIdx.x * 256 + threadIdx.x) * 8;
    if (i >= j.n[z]) return;
    float4 f0 = *(const float4*)(j.src[z] + i);
    float4 f1 = *(const float4*)(j.src[z] + i + 4);
    uint4 o;
    o.x = pack2(f0.x, f0.y); o.y = pack2(f0.z, f0.w);
    o.z = pack2(f1.x, f1.y); o.w = pack2(f1.z, f1.w);
    *(uint4*)(j.dst[z] + i) = o;
}

// ---------------- FP16 GEMM, half inputs, double-buffered pipeline ----------------
struct GemmJobs {
    const __half* W[3];
    const float*  bias[3];
    const float*  res[3];
    float*        out[3];
    int           norm[3];   // 1 => fused rmsnorm+rope epilogue (q/k jobs)
};

__global__ __launch_bounds__(256, 2)
void gemm_fp16_kernel(const __half* __restrict__ A, GemmJobs jobs,
                      const float* __restrict__ nw, int M, int N, int K)
{
    __shared__ __align__(16) uint32_t As[2][2048];  // [ks2][mt8][lane32][reg4] 8KB each
    __shared__ __align__(16) uint32_t Bs[2][2048];  // [ks2][nt16][lane32][reg2] 8KB each

    const int z = blockIdx.z;
    const __half* W   = jobs.W[z];
    const float* bias = jobs.bias[z];
    const float* res  = jobs.res[z];
    float*       C    = jobs.out[z];
    const int    donorm = jobs.norm[z];

    const int tid = threadIdx.x;
    const int lane = tid & 31;
    const int wid = tid >> 5;
    const int wm = wid & 3, wn = wid >> 2;
    const int m0 = blockIdx.y * 128, n0 = blockIdx.x * 128;

    // A loader: rows {r, r+8}, cols aks*8..+7 of the 128x32 chunk
    const int amt = tid >> 5, ag = (tid >> 2) & 7, aks = tid & 3;
    const int aksh = aks >> 1, ahk = aks & 1;
    const int axor = ((ag >> 1) & 1) | (aksh << 1);
    const __half* Ap = A + (size_t)(m0 + amt * 16 + ag) * K + aks * 8;
    // B loader: one W row, 16 cols (one k16 step)
    const int bnt = ((tid >> 5) << 1) | (tid & 1);
    const int bg = (tid >> 2) & 7;
    const int bks = (tid >> 1) & 1;
    const int bxr = (tid & 1) | (bks << 1);
    const __half* Wp = W + (size_t)(n0 + bnt * 8 + bg) * K + bks * 16;

    float acc[2][8][4];
#pragma unroll
    for (int mi = 0; mi < 2; mi++)
#pragma unroll
        for (int ni = 0; ni < 8; ni++)
#pragma unroll
            for (int e = 0; e < 4; e++) acc[mi][ni][e] = 0.f;

    const int NCH = K / 32;
    uint4 a_lo = *(const uint4*)(Ap);
    uint4 a_hi = *(const uint4*)(Ap + (size_t)8 * K);
    uint4 w_lo = *(const uint4*)(Wp);
    uint4 w_hi = *(const uint4*)(Wp + 8);

    for (int kt = 0; kt < NCH; kt++) {
        const int p = kt & 1;
        // ---- store staged chunk into buffer p (halves already fragment pairs) ----
        {
            const uint32_t* alo = (const uint32_t*)&a_lo;
            const uint32_t* ahi = (const uint32_t*)&a_hi;
            const uint32_t* wlo = (const uint32_t*)&w_lo;
            const uint32_t* whi = (const uint32_t*)&w_hi;
#pragma unroll
            for (int t = 0; t < 4; t++) {
                int aslot = (aksh * 8 + amt) * 32 + 4 * ag + (t ^ axor);
                *(uint2*)&As[p][aslot * 4 + 2 * ahk] = make_uint2(alo[t], ahi[t]);
                int bslot = (bks * 16 + bnt) * 32 + 4 * bg + (t ^ bxr);
                *(uint2*)&Bs[p][bslot * 2] = make_uint2(wlo[t], whi[t]);
            }
        }
        __syncthreads();
        // ---- prefetch next chunk (overlaps with compute below) ----
        if (kt + 1 < NCH) {
            int off = (kt + 1) * 32;
            a_lo = *(const uint4*)(Ap + off);
            a_hi = *(const uint4*)(Ap + off + (size_t)8 * K);
            w_lo = *(const uint4*)(Wp + off);
            w_hi = *(const uint4*)(Wp + off + 8);
        }
        // ---- compute from buffer p ----
#pragma unroll
        for (int ks = 0; ks < 2; ks++) {
            uint2 bb[8];
#pragma unroll
            for (int ni = 0; ni < 8; ni++) {
                int nt = wn * 8 + ni;
                int x = (nt & 1) | (ks << 1);
                int s = (ks * 16 + nt) * 32 + (lane & 28) + ((lane & 3) ^ x);
                bb[ni] = *(const uint2*)&Bs[p][s * 2];
            }
            int xa = ((lane >> 3) & 1) | (ks << 1);
            uint4 aa[2];
#pragma unroll
            for (int mi = 0; mi < 2; mi++) {
                int s = (ks * 8 + wm * 2 + mi) * 32 + (lane & 28) + ((lane & 3) ^ xa);
                aa[mi] = *(const uint4*)&As[p][s * 4];
            }
#pragma unroll
            for (int mi = 0; mi < 2; mi++)
#pragma unroll
                for (int ni = 0; ni < 8; ni++)
                    mma16(acc[mi][ni], (const uint32_t*)&aa[mi], (const uint32_t*)&bb[ni]);
        }
    }

    const int g = lane >> 2, t = lane & 3;
    if (donorm) {
#pragma unroll
        for (int mi = 0; mi < 2; mi++) {
#pragma unroll
            for (int h = 0; h < 2; h++) {
                int m = m0 + wm * 32 + mi * 16 + h * 8 + g;
                int s = m & (N_CTX - 1);
                float v0[8], v1[8];
                float ss = 0.f;
#pragma unroll
                for (int ni = 0; ni < 8; ni++) {
                    int n = n0 + wn * 64 + ni * 8 + 2 * t;
                    float e0 = acc[mi][ni][h * 2 + 0] + bias[n];
                    float e1 = acc[mi][ni][h * 2 + 1] + bias[n + 1];
                    v0[ni] = e0; v1[ni] = e1;
                    ss = fmaf(e0, e0, fmaf(e1, e1, ss));
                }
                ss += __shfl_xor_sync(0xffffffffu, ss, 1);
                ss += __shfl_xor_sync(0xffffffffu, ss, 2);
                float r = rsqrtf(ss * (1.0f / 64.0f) + 1.1920929e-07f);
#pragma unroll
                for (int ni = 0; ni < 8; ni++) {
                    int d = ni * 8 + 2 * t;
                    float y0 = v0[ni] * r * nw[d];
                    float y1 = v1[ni] * r * nw[d + 1];
                    int j0 = d & 31, j1 = (d + 1) & 31;
                    float o0 = y0 * g_cos[s * 32 + j0] - y1 * g_sin[s * 32 + j0];
                    float o1 = y1 * g_cos[s * 32 + j1] + y0 * g_sin[s * 32 + j1];
                    int n = n0 + wn * 64 + d;
                    *(float2*)&C[(size_t)m * N + n] = make_float2(o0, o1);
                }
            }
        }
    } else {
#pragma unroll
        for (int mi = 0; mi < 2; mi++) {
#pragma unroll
            for (int h = 0; h < 2; h++) {
                int m = m0 + wm * 32 + mi * 16 + h * 8 + g;
#pragma unroll
                for (int ni = 0; ni < 8; ni++) {
                    int n = n0 + wn * 64 + ni * 8 + 2 * t;
                    float2 v = make_float2(acc[mi][ni][h * 2 + 0], acc[mi][ni][h * 2 + 1]);
                    if (bias) { v.x += bias[n]; v.y += bias[n + 1]; }
                    if (res) {
                        float2 r = *(const float2*)&res[(size_t)m * N + n];
                        v.x += r.x; v.y += r.y;
                    }
                    *(float2*)&C[(size_t)m * N + n] = v;
                }
            }
        }
    }
}

// ---------------- fused quadratic causal attention, FP16 mma (R11 proven, Z->half) ----------------
#define QH_OFF 0
#define KH_OFF 16384
#define VH_OFF (16384 + 8192)
#define ATTN_SMEM (16384 + 8192 + 9216)   /* 33792 B */

__global__ __launch_bounds__(128)
void attn_fp16_kernel(const float* __restrict__ Q, const float* __restrict__ Kg,
                      const float* __restrict__ V, __half* __restrict__ Z)
{
    extern __shared__ char smc[];
    uint4* Qh = (uint4*)(smc + QH_OFF);     // [ks4][mt8][lane32]
    uint2* Kh = (uint2*)(smc + KH_OFF);     // [ks4][nt8][lane32]
    uint2* Vh = (uint2*)(smc + VH_OFF);     // [cp4][dn8][36 padded slots]

    const int tid = threadIdx.x;
    const int lane = tid & 31;
    const int wp = tid >> 5;
    const int g = lane >> 2, t = lane & 3;
    const int bh = blockIdx.y;
    const int b = bh >> 4, h = bh & 15;
    const int jt = (int)gridDim.x - 1 - (int)blockIdx.x;   // big tiles first
    const size_t base = (size_t)(b * N_CTX) * D_MODEL + h * 64;
    const int nkt = 2 * jt + 2;

    // ---- Q tile (128 x 64) -> A-frag smem, once ----
    {
        const int qmt = tid >> 4;
        const int qg = (tid >> 1) & 7;
        const int dh = tid & 1;
        const float* qp0 = Q + base + (size_t)(jt * 128 + qmt * 16 + qg) * D_MODEL + dh * 32;
        const float* qp1 = qp0 + (size_t)8 * D_MODEL;
#pragma unroll
        for (int kl = 0; kl < 2; kl++) {
            float v0[16], v1[16];
#pragma unroll
            for (int i = 0; i < 4; i++) {
                *(float4*)&v0[4 * i] = *(const float4*)(qp0 + kl * 16 + 4 * i);
                *(float4*)&v1[4 * i] = *(const float4*)(qp1 + kl * 16 + 4 * i);
            }
            int ks = dh * 2 + kl;
            int x = ((qg >> 1) & 1) | ((ks >> 1) << 1);
#pragma unroll
            for (int tt = 0; tt < 4; tt++) {
                Qh[(ks * 8 + qmt) * 32 + qg * 4 + (tt ^ x)] =
                    make_uint4(pack2(v0[2 * tt], v0[2 * tt + 1]),
                               pack2(v1[2 * tt], v1[2 * tt + 1]),
                               pack2(v0[2 * tt + 8], v0[2 * tt + 9]),
                               pack2(v1[2 * tt + 8], v1[2 * tt + 9]));
            }
        }
    }

    float zacc[2][8][4];
#pragma unroll
    for (int mm = 0; mm < 2; mm++)
#pragma unroll
        for (int i = 0; i < 8; i++)
#pragma unroll
            for (int j = 0; j < 4; j++) zacc[mm][i][j] = 0.f;

    const int kr = tid & 63, ksh = tid >> 6;
    const int knt = kr >> 3, kg = kr & 7;
    const int kx = (kg >> 2) | ((knt & 1) << 1);
    const int vcp = tid >> 5;
    const int vdq = (tid >> 2) & 7;
    const int vt = tid & 3;

    const float* kbase = Kg + base;
    const float* vbase = V + base;

    const float inv64 = 1.0f / 64.0f;
    const int qbase = jt * 128 + wp * 32;

    for (int kt = 0; kt < nkt; ++kt) {
        const int ktb = kt * 64;
        __syncthreads();

        // ---- K tile -> B-frag smem ----
        {
            const float* kp = kbase + (size_t)(ktb + kr) * D_MODEL + ksh * 32;
            float v[32];
#pragma unroll
            for (int i = 0; i < 8; i++)
                *(float4*)&v[4 * i] = *(const float4*)(kp + 4 * i);
#pragma unroll
            for (int kl = 0; kl < 2; kl++) {
                int ks = ksh * 2 + kl;
#pragma unroll
                for (int tt = 0; tt < 4; tt++) {
                    Kh[(ks * 8 + knt) * 32 + kg * 4 + (tt ^ kx)] =
                        make_uint2(pack2(v[16 * kl + 2 * tt], v[16 * kl + 2 * tt + 1]),
                                   pack2(v[16 * kl + 2 * tt + 8], v[16 * kl + 2 * tt + 9]));
                }
            }
        }
        // ---- V tile -> B-frag smem (keys packed in half2, stride-36 pad) ----
        {
            int ra = ktb + 16 * vcp + 2 * vt;
            const float* pa = vbase + (size_t)ra * D_MODEL + vdq * 8;
            const float* pb = pa + (size_t)1 * D_MODEL;
            const float* pc = pa + (size_t)8 * D_MODEL;
            const float* pd = pa + (size_t)9 * D_MODEL;
            float a[8], bb[8], c[8], d8[8];
            *(float4*)&a[0]  = *(const float4*)(pa);     *(float4*)&a[4]  = *(const float4*)(pa + 4);
            *(float4*)&bb[0] = *(const float4*)(pb);     *(float4*)&bb[4] = *(const float4*)(pb + 4);
            *(float4*)&c[0]  = *(const float4*)(pc);     *(float4*)&c[4]  = *(const float4*)(pc + 4);
            *(float4*)&d8[0] = *(const float4*)(pd);     *(float4*)&d8[4] = *(const float4*)(pd + 4);
#pragma unroll
            for (int i = 0; i < 8; i++) {
                Vh[(vcp * 8 + vdq) * 36 + i * 4 + vt] =
                    make_uint2(pack2(a[i], bb[i]), pack2(c[i], d8[i]));
            }
        }
        __syncthreads();

        // ---- GEMM1: S[32 x 64] per warp ----
        float sacc[2][8][4];
#pragma unroll
        for (int mm = 0; mm < 2; mm++)
#pragma unroll
            for (int i = 0; i < 8; i++)
#pragma unroll
                for (int j = 0; j < 4; j++) sacc[mm][i][j] = 0.f;

#pragma unroll
        for (int ks = 0; ks < 4; ks++) {
            int qx = ((g >> 1) & 1) | ((ks >> 1) << 1);
            uint4 qa0 = Qh[(ks * 8 + wp * 2 + 0) * 32 + g * 4 + (t ^ qx)];
            uint4 qa1 = Qh[(ks * 8 + wp * 2 + 1) * 32 + g * 4 + (t ^ qx)];
#pragma unroll
            for (int nt = 0; nt < 8; nt++) {
                int xk = (g >> 2) | ((nt & 1) << 1);
                uint2 kb = Kh[(ks * 8 + nt) * 32 + g * 4 + (t ^ xk)];
                mma16(sacc[0][nt], (const uint32_t*)&qa0, (const uint32_t*)&kb);
                mma16(sacc[1][nt], (const uint32_t*)&qa1, (const uint32_t*)&kb);
            }
        }

        // ---- P = (S/64)^2 * causal -> direct A-frag pack; GEMM2 ----
#pragma unroll
        for (int cp = 0; cp < 4; cp++) {
            uint2 vb[8];
#pragma unroll
            for (int dn = 0; dn < 8; dn++)
                vb[dn] = Vh[(cp * 8 + dn) * 36 + g * 4 + t];
#pragma unroll
            for (int mm = 0; mm < 2; mm++) {
                int qr0 = qbase + mm * 16 + g;
                int qr1 = qr0 + 8;
                int c0 = 2 * cp, c1 = 2 * cp + 1;
                int kc0 = ktb + c0 * 8 + 2 * t;
                int kc1 = ktb + c1 * 8 + 2 * t;
                float p00 = sacc[mm][c0][0] * inv64; p00 *= p00; if (kc0 > qr0)     p00 = 0.f;
                float p01 = sacc[mm][c0][1] * inv64; p01 *= p01; if (kc0 + 1 > qr0) p01 = 0.f;
                float p02 = sacc[mm][c0][2] * inv64; p02 *= p02; if (kc0 > qr1)     p02 = 0.f;
                float p03 = sacc[mm][c0][3] * inv64; p03 *= p03; if (kc0 + 1 > qr1) p03 = 0.f;
                float p10 = sacc[mm][c1][0] * inv64; p10 *= p10; if (kc1 > qr0)     p10 = 0.f;
                float p11 = sacc[mm][c1][1] * inv64; p11 *= p11; if (kc1 + 1 > qr0) p11 = 0.f;
                float p12 = sacc[mm][c1][2] * inv64; p12 *= p12; if (kc1 > qr1)     p12 = 0.f;
                float p13 = sacc[mm][c1][3] * inv64; p13 *= p13; if (kc1 + 1 > qr1) p13 = 0.f;
                uint32_t af[4];
                af[0] = pack2(p00, p01);
                af[1] = pack2(p02, p03);
                af[2] = pack2(p10, p11);
                af[3] = pack2(p12, p13);
#pragma unroll
                for (int dn = 0; dn < 8; dn++)
                    mma16(zacc[mm][dn], af, (const uint32_t*)&vb[dn]);
            }
        }
    }

    // ---- write Z (fp16) ----
#pragma unroll
    for (int mm = 0; mm < 2; mm++) {
        int qr0 = qbase + mm * 16 + g;
        int qr1 = qr0 + 8;
#pragma unroll
        for (int dn = 0; dn < 8; dn++) {
            int col = dn * 8 + 2 * t;
            *(uint32_t*)&Z[base + (size_t)qr0 * D_MODEL + col] =
                pack2(zacc[mm][dn][0], zacc[mm][dn][1]);
            *(uint32_t*)&Z[base + (size_t)qr1 * D_MODEL + col] =
                pack2(zacc[mm][dn][2], zacc[mm][dn][3]);
        }
    }
}

// ---------------- launch ----------------
extern "C" void kernel_launch(void* const* d_in, const int* in_sizes, int n_in,
                              void* d_out, int out_size)
{
    const float* x  = (const float*)d_in[0];
    const float* Wq = (const float*)d_in[1];
    const float* bq = (const float*)d_in[2];
    const float* Wk = (const float*)d_in[3];
    const float* bk = (const float*)d_in[4];
    const float* Wv = (const float*)d_in[5];
    const float* bv = (const float*)d_in[6];
    const float* Wo = (const float*)d_in[7];
    const float* nw = (const float*)d_in[8];
    float* out = (float*)d_out;

    float *q, *k, *v;
    __half *zh, *xh, *wqh, *wkh, *wvh, *woh;
    cudaGetSymbolAddress((void**)&q,   g_q);
    cudaGetSymbolAddress((void**)&k,   g_k);
    cudaGetSymbolAddress((void**)&v,   g_v);
    cudaGetSymbolAddress((void**)&zh,  g_zh);
    cudaGetSymbolAddress((void**)&xh,  g_xh);
    cudaGetSymbolAddress((void**)&wqh, g_wqh);
    cudaGetSymbolAddress((void**)&wkh, g_wkh);
    cudaGetSymbolAddress((void**)&wvh, g_wvh);
    cudaGetSymbolAddress((void**)&woh, g_woh);

    cudaFuncSetAttribute(attn_fp16_kernel, cudaFuncAttributeMaxDynamicSharedMemorySize, ATTN_SMEM);

    rope_cache_kernel<<<64, 1024>>>();

    // convert x + 4 weight matrices to fp16
    CvtJobs cj;
    cj.src[0] = x;  cj.dst[0] = xh;  cj.n[0] = MTOT * D_MODEL;
    cj.src[1] = Wq; cj.dst[1] = wqh; cj.n[1] = D_MODEL * D_MODEL;
    cj.src[2] = Wk; cj.dst[2] = wkh; cj.n[2] = D_MODEL * D_MODEL;
    cj.src[3] = Wv; cj.dst[3] = wvh; cj.n[3] = D_MODEL * D_MODEL;
    cj.src[4] = Wo; cj.dst[4] = woh; cj.n[4] = D_MODEL * D_MODEL;
    cvt_kernel<<<dim3(MTOT * D_MODEL / (256 * 8), 5), 256>>>(cj);

    // QKV projections: one launch, 3 jobs; q/k get fused rmsnorm+rope epilogue
    GemmJobs jq;
    jq.W[0] = wqh; jq.W[1] = wkh; jq.W[2] = wvh;
    jq.bias[0] = bq; jq.bias[1] = bk; jq.bias[2] = bv;
    jq.res[0] = nullptr; jq.res[1] = nullptr; jq.res[2] = nullptr;
    jq.out[0] = q; jq.out[1] = k; jq.out[2] = v;
    jq.norm[0] = 1; jq.norm[1] = 1; jq.norm[2] = 0;
    gemm_fp16_kernel<<<dim3(D_MODEL / 128, MTOT / 128, 3), 256>>>(xh, jq, nw, MTOT, D_MODEL, D_MODEL);

    attn_fp16_kernel<<<dim3(16, 32), 128, ATTN_SMEM>>>(q, k, v, zh);

    // output projection + residual
    GemmJobs jo;
    jo.W[0] = woh; jo.W[1] = nullptr; jo.W[2] = nullptr;
    jo.bias[0] = nullptr; jo.bias[1] = nullptr; jo.bias[2] = nullptr;
    jo.res[0] = x; jo.res[1] = nullptr; jo.res[2] = nullptr;
    jo.out[0] = out; jo.out[1] = nullptr; jo.out[2] = nullptr;
    jo.norm[0] = 0; jo.norm[1] = 0; jo.norm[2] = 0;
    gemm_fp16_kernel<<<dim3(D_MODEL / 128, MTOT / 128, 1), 256>>>(zh, jo, nw, MTOT, D_MODEL, D_MODEL);
}

// round 14
// speedup vs baseline: 1.4877x; 1.0692x over previous
#include <cuda_runtime.h>
#include <cuda_fp16.h>
#include <math.h>
#include <stdint.h>

#define D_MODEL 1024
#define N_HEAD  16
#define D_HEAD  64
#define N_CTX   2048
#define BATCH   2
#define MTOT    (BATCH * N_CTX)   /* 4096 rows */

// ---------------- scratch ----------------
__device__ __half g_qh[MTOT * D_MODEL];
__device__ __half g_kh[MTOT * D_MODEL];
__device__ __half g_vh[MTOT * D_MODEL];
__device__ __half g_zh[MTOT * D_MODEL];
__device__ __half g_xh[MTOT * D_MODEL];
__device__ __half g_wqh[D_MODEL * D_MODEL];
__device__ __half g_wkh[D_MODEL * D_MODEL];
__device__ __half g_wvh[D_MODEL * D_MODEL];
__device__ __half g_woh[D_MODEL * D_MODEL];
__device__ float  g_cos[N_CTX * 32];
__device__ float  g_sin[N_CTX * 32];

// ---------------- helpers ----------------
__device__ __forceinline__ uint32_t pack2(float x, float y) {
    __half2 h = __floats2half2_rn(x, y);
    return *(uint32_t*)&h;
}

// fp16 m16n8k16
__device__ __forceinline__ void mma16(float c[4], const uint32_t* a, const uint32_t* b) {
    asm volatile(
        "mma.sync.aligned.m16n8k16.row.col.f32.f16.f16.f32 "
        "{%0,%1,%2,%3}, {%4,%5,%6,%7}, {%8,%9}, {%0,%1,%2,%3};\n"
        : "+f"(c[0]), "+f"(c[1]), "+f"(c[2]), "+f"(c[3])
        : "r"(a[0]), "r"(a[1]), "r"(a[2]), "r"(a[3]), "r"(b[0]), "r"(b[1]));
}

// ---------------- RoPE table ----------------
__global__ void rope_cache_kernel() {
    int i = blockIdx.x * blockDim.x + threadIdx.x;
    int t = i >> 5;
    int j = i & 31;
    float invf = (float)pow(10000.0, -(double)j / 32.0);
    double ang = (double)t * (double)invf;
    double sv, cv;
    sincos(ang, &sv, &cv);
    g_cos[i] = (float)cv;
    g_sin[i] = (float)sv;
}

// ---------------- fp32 -> fp16 conversion (x + 4 weight matrices) ----------------
struct CvtJobs {
    const float* src[5];
    __half*      dst[5];
    int          n[5];
};

__global__ __launch_bounds__(256)
void cvt_kernel(CvtJobs j) {
    int z = blockIdx.y;
    int i = (blockIdx.x * 256 + threadIdx.x) * 8;
    if (i >= j.n[z]) return;
    float4 f0 = *(const float4*)(j.src[z] + i);
    float4 f1 = *(const float4*)(j.src[z] + i + 4);
    uint4 o;
    o.x = pack2(f0.x, f0.y); o.y = pack2(f0.z, f0.w);
    o.z = pack2(f1.x, f1.y); o.w = pack2(f1.z, f1.w);
    *(uint4*)(j.dst[z] + i) = o;
}

// ---------------- FP16 GEMM, half in, double-buffered; half or float out ----------------
struct GemmJobs {
    const __half* W[3];
    const float*  bias[3];
    const float*  res[3];
    void*         out[3];
    int           norm[3];      // 1 => fused rmsnorm+rope epilogue, half out
    int           outhalf[3];   // 1 => half out (v job)
};

__global__ __launch_bounds__(256, 2)
void gemm_fp16_kernel(const __half* __restrict__ A, GemmJobs jobs,
                      const float* __restrict__ nw, int M, int N, int K)
{
    __shared__ __align__(16) uint32_t As[2][2048];
    __shared__ __align__(16) uint32_t Bs[2][2048];

    const int z = blockIdx.z;
    const __half* W   = jobs.W[z];
    const float* bias = jobs.bias[z];
    const float* res  = jobs.res[z];
    const int    donorm = jobs.norm[z];
    const int    ohalf  = jobs.outhalf[z];

    const int tid = threadIdx.x;
    const int lane = tid & 31;
    const int wid = tid >> 5;
    const int wm = wid & 3, wn = wid >> 2;
    const int m0 = blockIdx.y * 128, n0 = blockIdx.x * 128;

    const int amt = tid >> 5, ag = (tid >> 2) & 7, aks = tid & 3;
    const int aksh = aks >> 1, ahk = aks & 1;
    const int axor = ((ag >> 1) & 1) | (aksh << 1);
    const __half* Ap = A + (size_t)(m0 + amt * 16 + ag) * K + aks * 8;
    const int bnt = ((tid >> 5) << 1) | (tid & 1);
    const int bg = (tid >> 2) & 7;
    const int bks = (tid >> 1) & 1;
    const int bxr = (tid & 1) | (bks << 1);
    const __half* Wp = W + (size_t)(n0 + bnt * 8 + bg) * K + bks * 16;

    float acc[2][8][4];
#pragma unroll
    for (int mi = 0; mi < 2; mi++)
#pragma unroll
        for (int ni = 0; ni < 8; ni++)
#pragma unroll
            for (int e = 0; e < 4; e++) acc[mi][ni][e] = 0.f;

    const int NCH = K / 32;
    uint4 a_lo = *(const uint4*)(Ap);
    uint4 a_hi = *(const uint4*)(Ap + (size_t)8 * K);
    uint4 w_lo = *(const uint4*)(Wp);
    uint4 w_hi = *(const uint4*)(Wp + 8);

    for (int kt = 0; kt < NCH; kt++) {
        const int p = kt & 1;
        {
            const uint32_t* alo = (const uint32_t*)&a_lo;
            const uint32_t* ahi = (const uint32_t*)&a_hi;
            const uint32_t* wlo = (const uint32_t*)&w_lo;
            const uint32_t* whi = (const uint32_t*)&w_hi;
#pragma unroll
            for (int t = 0; t < 4; t++) {
                int aslot = (aksh * 8 + amt) * 32 + 4 * ag + (t ^ axor);
                *(uint2*)&As[p][aslot * 4 + 2 * ahk] = make_uint2(alo[t], ahi[t]);
                int bslot = (bks * 16 + bnt) * 32 + 4 * bg + (t ^ bxr);
                *(uint2*)&Bs[p][bslot * 2] = make_uint2(wlo[t], whi[t]);
            }
        }
        __syncthreads();
        if (kt + 1 < NCH) {
            int off = (kt + 1) * 32;
            a_lo = *(const uint4*)(Ap + off);
            a_hi = *(const uint4*)(Ap + off + (size_t)8 * K);
            w_lo = *(const uint4*)(Wp + off);
            w_hi = *(const uint4*)(Wp + off + 8);
        }
#pragma unroll
        for (int ks = 0; ks < 2; ks++) {
            uint2 bb[8];
#pragma unroll
            for (int ni = 0; ni < 8; ni++) {
                int nt = wn * 8 + ni;
                int x = (nt & 1) | (ks << 1);
                int s = (ks * 16 + nt) * 32 + (lane & 28) + ((lane & 3) ^ x);
                bb[ni] = *(const uint2*)&Bs[p][s * 2];
            }
            int xa = ((lane >> 3) & 1) | (ks << 1);
            uint4 aa[2];
#pragma unroll
            for (int mi = 0; mi < 2; mi++) {
                int s = (ks * 8 + wm * 2 + mi) * 32 + (lane & 28) + ((lane & 3) ^ xa);
                aa[mi] = *(const uint4*)&As[p][s * 4];
            }
#pragma unroll
            for (int mi = 0; mi < 2; mi++)
#pragma unroll
                for (int ni = 0; ni < 8; ni++)
                    mma16(acc[mi][ni], (const uint32_t*)&aa[mi], (const uint32_t*)&bb[ni]);
        }
    }

    const int g = lane >> 2, t = lane & 3;
    if (donorm) {
        __half* Ch = (__half*)jobs.out[z];
#pragma unroll
        for (int mi = 0; mi < 2; mi++) {
#pragma unroll
            for (int h = 0; h < 2; h++) {
                int m = m0 + wm * 32 + mi * 16 + h * 8 + g;
                int s = m & (N_CTX - 1);
                float v0[8], v1[8];
                float ss = 0.f;
#pragma unroll
                for (int ni = 0; ni < 8; ni++) {
                    int n = n0 + wn * 64 + ni * 8 + 2 * t;
                    float e0 = acc[mi][ni][h * 2 + 0] + bias[n];
                    float e1 = acc[mi][ni][h * 2 + 1] + bias[n + 1];
                    v0[ni] = e0; v1[ni] = e1;
                    ss = fmaf(e0, e0, fmaf(e1, e1, ss));
                }
                ss += __shfl_xor_sync(0xffffffffu, ss, 1);
                ss += __shfl_xor_sync(0xffffffffu, ss, 2);
                float r = rsqrtf(ss * (1.0f / 64.0f) + 1.1920929e-07f);
#pragma unroll
                for (int ni = 0; ni < 8; ni++) {
                    int d = ni * 8 + 2 * t;
                    float y0 = v0[ni] * r * nw[d];
                    float y1 = v1[ni] * r * nw[d + 1];
                    int j0 = d & 31, j1 = (d + 1) & 31;
                    float o0 = y0 * g_cos[s * 32 + j0] - y1 * g_sin[s * 32 + j0];
                    float o1 = y1 * g_cos[s * 32 + j1] + y0 * g_sin[s * 32 + j1];
                    int n = n0 + wn * 64 + d;
                    *(uint32_t*)&Ch[(size_t)m * N + n] = pack2(o0, o1);
                }
            }
        }
    } else if (ohalf) {
        __half* Ch = (__half*)jobs.out[z];
#pragma unroll
        for (int mi = 0; mi < 2; mi++) {
#pragma unroll
            for (int h = 0; h < 2; h++) {
                int m = m0 + wm * 32 + mi * 16 + h * 8 + g;
#pragma unroll
                for (int ni = 0; ni < 8; ni++) {
                    int n = n0 + wn * 64 + ni * 8 + 2 * t;
                    float e0 = acc[mi][ni][h * 2 + 0];
                    float e1 = acc[mi][ni][h * 2 + 1];
                    if (bias) { e0 += bias[n]; e1 += bias[n + 1]; }
                    *(uint32_t*)&Ch[(size_t)m * N + n] = pack2(e0, e1);
                }
            }
        }
    } else {
        float* C = (float*)jobs.out[z];
#pragma unroll
        for (int mi = 0; mi < 2; mi++) {
#pragma unroll
            for (int h = 0; h < 2; h++) {
                int m = m0 + wm * 32 + mi * 16 + h * 8 + g;
#pragma unroll
                for (int ni = 0; ni < 8; ni++) {
                    int n = n0 + wn * 64 + ni * 8 + 2 * t;
                    float2 v = make_float2(acc[mi][ni][h * 2 + 0], acc[mi][ni][h * 2 + 1]);
                    if (bias) { v.x += bias[n]; v.y += bias[n + 1]; }
                    if (res) {
                        float2 r = *(const float2*)&res[(size_t)m * N + n];
                        v.x += r.x; v.y += r.y;
                    }
                    *(float2*)&C[(size_t)m * N + n] = v;
                }
            }
        }
    }
}

// ---------------- fused quadratic causal attention, FP16 in/out ----------------
// CTA: 128 threads (4 warps), q-tile 128; warp owns 32 q-rows x full 64-k.
// Half inputs: Q/K loaders are pure uint4 repacks; V pairs keys via byte_perm.
#define QH_OFF 0
#define KH_OFF 16384
#define VH_OFF (16384 + 8192)
#define ATTN_SMEM (16384 + 8192 + 9216)   /* 33792 B */

__global__ __launch_bounds__(128)
void attn_fp16_kernel(const __half* __restrict__ Q, const __half* __restrict__ Kg,
                      const __half* __restrict__ V, __half* __restrict__ Z)
{
    extern __shared__ char smc[];
    uint4* Qh = (uint4*)(smc + QH_OFF);     // [ks4][mt8][lane32]
    uint2* Kh = (uint2*)(smc + KH_OFF);     // [ks4][nt8][lane32]
    uint2* Vh = (uint2*)(smc + VH_OFF);     // [cp4][dn8][36 padded slots]

    const int tid = threadIdx.x;
    const int lane = tid & 31;
    const int wp = tid >> 5;
    const int g = lane >> 2, t = lane & 3;
    const int bh = blockIdx.y;
    const int b = bh >> 4, h = bh & 15;
    const int jt = (int)gridDim.x - 1 - (int)blockIdx.x;   // big tiles first
    const size_t base = (size_t)(b * N_CTX) * D_MODEL + h * 64;
    const int nkt = 2 * jt + 2;

    // ---- Q tile (128 x 64 half) -> A-frag smem, once (pure repack) ----
    {
        const int qmt = tid >> 4;           // 0..7
        const int qg = (tid >> 1) & 7;      // 0..7
        const int dh = tid & 1;             // 0..1
        const __half* qp0 = Q + base + (size_t)(jt * 128 + qmt * 16 + qg) * D_MODEL + dh * 32;
        const __half* qp1 = qp0 + (size_t)8 * D_MODEL;
#pragma unroll
        for (int kl = 0; kl < 2; kl++) {
            int ks = dh * 2 + kl;
            uint4 A0 = *(const uint4*)(qp0 + kl * 16);       // row r,  tslot 0..3
            uint4 B0 = *(const uint4*)(qp0 + kl * 16 + 8);   // row r,  tslot 4..7
            uint4 A1 = *(const uint4*)(qp1 + kl * 16);       // row r+8
            uint4 B1 = *(const uint4*)(qp1 + kl * 16 + 8);
            const uint32_t* a0 = (const uint32_t*)&A0;
            const uint32_t* b0 = (const uint32_t*)&B0;
            const uint32_t* a1 = (const uint32_t*)&A1;
            const uint32_t* b1 = (const uint32_t*)&B1;
            int x = ((qg >> 1) & 1) | ((ks >> 1) << 1);
#pragma unroll
            for (int tt = 0; tt < 4; tt++)
                Qh[(ks * 8 + qmt) * 32 + qg * 4 + (tt ^ x)] =
                    make_uint4(a0[tt], a1[tt], b0[tt], b1[tt]);
        }
    }

    float zacc[2][8][4];
#pragma unroll
    for (int mm = 0; mm < 2; mm++)
#pragma unroll
        for (int i = 0; i < 8; i++)
#pragma unroll
            for (int j = 0; j < 4; j++) zacc[mm][i][j] = 0.f;

    const int kr = tid & 63, ksh = tid >> 6;
    const int knt = kr >> 3, kg = kr & 7;
    const int kx = (kg >> 2) | ((knt & 1) << 1);
    const int vcp = tid >> 5;
    const int vdq = (tid >> 2) & 7;
    const int vt = tid & 3;

    const __half* kbase = Kg + base;
    const __half* vbase = V + base;

    const float inv64 = 1.0f / 64.0f;
    const int qbase = jt * 128 + wp * 32;

    for (int kt = 0; kt < nkt; ++kt) {
        const int ktb = kt * 64;
        __syncthreads();   // prev iteration consumers done (covers Q store at kt=0)

        // ---- K tile -> B-frag smem (pure repack) ----
        {
            const __half* kp = kbase + (size_t)(ktb + kr) * D_MODEL + ksh * 32;
#pragma unroll
            for (int kl = 0; kl < 2; kl++) {
                int ks = ksh * 2 + kl;
                uint4 A = *(const uint4*)(kp + kl * 16);
                uint4 B = *(const uint4*)(kp + kl * 16 + 8);
                const uint32_t* a = (const uint32_t*)&A;
                const uint32_t* b = (const uint32_t*)&B;
#pragma unroll
                for (int tt = 0; tt < 4; tt++)
                    Kh[(ks * 8 + knt) * 32 + kg * 4 + (tt ^ kx)] =
                        make_uint2(a[tt], b[tt]);
            }
        }
        // ---- V tile -> B-frag smem (key pairs via byte_perm, stride-36 pad) ----
        {
            int ra = ktb + 16 * vcp + 2 * vt;
            const __half* pa = vbase + (size_t)ra * D_MODEL + vdq * 8;
            uint4 A = *(const uint4*)(pa);
            uint4 B = *(const uint4*)(pa + (size_t)1 * D_MODEL);
            uint4 C = *(const uint4*)(pa + (size_t)8 * D_MODEL);
            uint4 D = *(const uint4*)(pa + (size_t)9 * D_MODEL);
            const uint32_t* a = (const uint32_t*)&A;
            const uint32_t* b = (const uint32_t*)&B;
            const uint32_t* c = (const uint32_t*)&C;
            const uint32_t* d = (const uint32_t*)&D;
#pragma unroll
            for (int i = 0; i < 8; i++) {
                int j = i >> 1;
                uint32_t sel = (i & 1) ? 0x7632u : 0x5410u;
                Vh[(vcp * 8 + vdq) * 36 + i * 4 + vt] =
                    make_uint2(__byte_perm(a[j], b[j], sel),
                               __byte_perm(c[j], d[j], sel));
            }
        }
        __syncthreads();

        // ---- GEMM1: S[32 x 64] per warp ----
        float sacc[2][8][4];
#pragma unroll
        for (int mm = 0; mm < 2; mm++)
#pragma unroll
            for (int i = 0; i < 8; i++)
#pragma unroll
                for (int j = 0; j < 4; j++) sacc[mm][i][j] = 0.f;

#pragma unroll
        for (int ks = 0; ks < 4; ks++) {
            int qx = ((g >> 1) & 1) | ((ks >> 1) << 1);
            uint4 qa0 = Qh[(ks * 8 + wp * 2 + 0) * 32 + g * 4 + (t ^ qx)];
            uint4 qa1 = Qh[(ks * 8 + wp * 2 + 1) * 32 + g * 4 + (t ^ qx)];
#pragma unroll
            for (int nt = 0; nt < 8; nt++) {
                int xk = (g >> 2) | ((nt & 1) << 1);
                uint2 kb = Kh[(ks * 8 + nt) * 32 + g * 4 + (t ^ xk)];
                mma16(sacc[0][nt], (const uint32_t*)&qa0, (const uint32_t*)&kb);
                mma16(sacc[1][nt], (const uint32_t*)&qa1, (const uint32_t*)&kb);
            }
        }

        // ---- P = (S/64)^2 * causal -> direct A-frag pack; GEMM2 ----
#pragma unroll
        for (int cp = 0; cp < 4; cp++) {
            uint2 vb[8];
#pragma unroll
            for (int dn = 0; dn < 8; dn++)
                vb[dn] = Vh[(cp * 8 + dn) * 36 + g * 4 + t];
#pragma unroll
            for (int mm = 0; mm < 2; mm++) {
                int qr0 = qbase + mm * 16 + g;
                int qr1 = qr0 + 8;
                int c0 = 2 * cp, c1 = 2 * cp + 1;
                int kc0 = ktb + c0 * 8 + 2 * t;
                int kc1 = ktb + c1 * 8 + 2 * t;
                float p00 = sacc[mm][c0][0] * inv64; p00 *= p00; if (kc0 > qr0)     p00 = 0.f;
                float p01 = sacc[mm][c0][1] * inv64; p01 *= p01; if (kc0 + 1 > qr0) p01 = 0.f;
                float p02 = sacc[mm][c0][2] * inv64; p02 *= p02; if (kc0 > qr1)     p02 = 0.f;
                float p03 = sacc[mm][c0][3] * inv64; p03 *= p03; if (kc0 + 1 > qr1) p03 = 0.f;
                float p10 = sacc[mm][c1][0] * inv64; p10 *= p10; if (kc1 > qr0)     p10 = 0.f;
                float p11 = sacc[mm][c1][1] * inv64; p11 *= p11; if (kc1 + 1 > qr0) p11 = 0.f;
                float p12 = sacc[mm][c1][2] * inv64; p12 *= p12; if (kc1 > qr1)     p12 = 0.f;
                float p13 = sacc[mm][c1][3] * inv64; p13 *= p13; if (kc1 + 1 > qr1) p13 = 0.f;
                uint32_t af[4];
                af[0] = pack2(p00, p01);
                af[1] = pack2(p02, p03);
                af[2] = pack2(p10, p11);
                af[3] = pack2(p12, p13);
#pragma unroll
                for (int dn = 0; dn < 8; dn++)
                    mma16(zacc[mm][dn], af, (const uint32_t*)&vb[dn]);
            }
        }
    }

    // ---- write Z (fp16) ----
#pragma unroll
    for (int mm = 0; mm < 2; mm++) {
        int qr0 = qbase + mm * 16 + g;
        int qr1 = qr0 + 8;
#pragma unroll
        for (int dn = 0; dn < 8; dn++) {
            int col = dn * 8 + 2 * t;
            *(uint32_t*)&Z[base + (size_t)qr0 * D_MODEL + col] =
                pack2(zacc[mm][dn][0], zacc[mm][dn][1]);
            *(uint32_t*)&Z[base + (size_t)qr1 * D_MODEL + col] =
                pack2(zacc[mm][dn][2], zacc[mm][dn][3]);
        }
    }
}

// ---------------- launch ----------------
extern "C" void kernel_launch(void* const* d_in, const int* in_sizes, int n_in,
                              void* d_out, int out_size)
{
    const float* x  = (const float*)d_in[0];
    const float* Wq = (const float*)d_in[1];
    const float* bq = (const float*)d_in[2];
    const float* Wk = (const float*)d_in[3];
    const float* bk = (const float*)d_in[4];
    const float* Wv = (const float*)d_in[5];
    const float* bv = (const float*)d_in[6];
    const float* Wo = (const float*)d_in[7];
    const float* nw = (const float*)d_in[8];
    float* out = (float*)d_out;

    __half *qh, *kh, *vh, *zh, *xh, *wqh, *wkh, *wvh, *woh;
    cudaGetSymbolAddress((void**)&qh,  g_qh);
    cudaGetSymbolAddress((void**)&kh,  g_kh);
    cudaGetSymbolAddress((void**)&vh,  g_vh);
    cudaGetSymbolAddress((void**)&zh,  g_zh);
    cudaGetSymbolAddress((void**)&xh,  g_xh);
    cudaGetSymbolAddress((void**)&wqh, g_wqh);
    cudaGetSymbolAddress((void**)&wkh, g_wkh);
    cudaGetSymbolAddress((void**)&wvh, g_wvh);
    cudaGetSymbolAddress((void**)&woh, g_woh);

    cudaFuncSetAttribute(attn_fp16_kernel, cudaFuncAttributeMaxDynamicSharedMemorySize, ATTN_SMEM);

    rope_cache_kernel<<<64, 1024>>>();

    // convert x + 4 weight matrices to fp16
    CvtJobs cj;
    cj.src[0] = x;  cj.dst[0] = xh;  cj.n[0] = MTOT * D_MODEL;
    cj.src[1] = Wq; cj.dst[1] = wqh; cj.n[1] = D_MODEL * D_MODEL;
    cj.src[2] = Wk; cj.dst[2] = wkh; cj.n[2] = D_MODEL * D_MODEL;
    cj.src[3] = Wv; cj.dst[3] = wvh; cj.n[3] = D_MODEL * D_MODEL;
    cj.src[4] = Wo; cj.dst[4] = woh; cj.n[4] = D_MODEL * D_MODEL;
    cvt_kernel<<<dim3(MTOT * D_MODEL / (256 * 8), 5), 256>>>(cj);

    // QKV projections: one launch, 3 jobs; q/k fused rmsnorm+rope, all half out
    GemmJobs jq;
    jq.W[0] = wqh; jq.W[1] = wkh; jq.W[2] = wvh;
    jq.bias[0] = bq; jq.bias[1] = bk; jq.bias[2] = bv;
    jq.res[0] = nullptr; jq.res[1] = nullptr; jq.res[2] = nullptr;
    jq.out[0] = qh; jq.out[1] = kh; jq.out[2] = vh;
    jq.norm[0] = 1; jq.norm[1] = 1; jq.norm[2] = 0;
    jq.outhalf[0] = 1; jq.outhalf[1] = 1; jq.outhalf[2] = 1;
    gemm_fp16_kernel<<<dim3(D_MODEL / 128, MTOT / 128, 3), 256>>>(xh, jq, nw, MTOT, D_MODEL, D_MODEL);

    attn_fp16_kernel<<<dim3(16, 32), 128, ATTN_SMEM>>>(qh, kh, vh, zh);

    // output projection + residual (fp32 out)
    GemmJobs jo;
    jo.W[0] = woh; jo.W[1] = nullptr; jo.W[2] = nullptr;
    jo.bias[0] = nullptr; jo.bias[1] = nullptr; jo.bias[2] = nullptr;
    jo.res[0] = x; jo.res[1] = nullptr; jo.res[2] = nullptr;
    jo.out[0] = out; jo.out[1] = nullptr; jo.out[2] = nullptr;
    jo.norm[0] = 0; jo.norm[1] = 0; jo.norm[2] = 0;
    jo.outhalf[0] = 0; jo.outhalf[1] = 0; jo.outhalf[2] = 0;
    gemm_fp16_kernel<<<dim3(D_MODEL / 128, MTOT / 128, 1), 256>>>(zh, jo, nw, MTOT, D_MODEL, D_MODEL);
}

// round 15
// speedup vs baseline: 1.5157x; 1.0189x over previous
#include <cuda_runtime.h>
#include <cuda_fp16.h>
#include <math.h>
#include <stdint.h>

#define D_MODEL 1024
#define N_HEAD  16
#define D_HEAD  64
#define N_CTX   2048
#define BATCH   2
#define MTOT    (BATCH * N_CTX)   /* 4096 rows */

// ---------------- scratch ----------------
__device__ __half g_qh[MTOT * D_MODEL];
__device__ __half g_kh[MTOT * D_MODEL];
__device__ __half g_vh[MTOT * D_MODEL];
__device__ __half g_zh[MTOT * D_MODEL];
__device__ __half g_xh[MTOT * D_MODEL];
__device__ __half g_wqh[D_MODEL * D_MODEL];
__device__ __half g_wkh[D_MODEL * D_MODEL];
__device__ __half g_wvh[D_MODEL * D_MODEL];
__device__ __half g_woh[D_MODEL * D_MODEL];
__device__ float  g_cos[N_CTX * 32];
__device__ float  g_sin[N_CTX * 32];

// ---------------- helpers ----------------
__device__ __forceinline__ uint32_t pack2(float x, float y) {
    __half2 h = __floats2half2_rn(x, y);
    return *(uint32_t*)&h;
}

// fp16 m16n8k16
__device__ __forceinline__ void mma16(float c[4], const uint32_t* a, const uint32_t* b) {
    asm volatile(
        "mma.sync.aligned.m16n8k16.row.col.f32.f16.f16.f32 "
        "{%0,%1,%2,%3}, {%4,%5,%6,%7}, {%8,%9}, {%0,%1,%2,%3};\n"
        : "+f"(c[0]), "+f"(c[1]), "+f"(c[2]), "+f"(c[3])
        : "r"(a[0]), "r"(a[1]), "r"(a[2]), "r"(a[3]), "r"(b[0]), "r"(b[1]));
}

// ---------------- RoPE table ----------------
__global__ void rope_cache_kernel() {
    int i = blockIdx.x * blockDim.x + threadIdx.x;
    int t = i >> 5;
    int j = i & 31;
    float invf = (float)pow(10000.0, -(double)j / 32.0);
    double ang = (double)t * (double)invf;
    double sv, cv;
    sincos(ang, &sv, &cv);
    g_cos[i] = (float)cv;
    g_sin[i] = (float)sv;
}

// ---------------- fp32 -> fp16 conversion (x + 4 weight matrices) ----------------
struct CvtJobs {
    const float* src[5];
    __half*      dst[5];
    int          n[5];
};

__global__ __launch_bounds__(256)
void cvt_kernel(CvtJobs j) {
    int z = blockIdx.y;
    int i = (blockIdx.x * 256 + threadIdx.x) * 8;
    if (i >= j.n[z]) return;
    float4 f0 = *(const float4*)(j.src[z] + i);
    float4 f1 = *(const float4*)(j.src[z] + i + 4);
    uint4 o;
    o.x = pack2(f0.x, f0.y); o.y = pack2(f0.z, f0.w);
    o.z = pack2(f1.x, f1.y); o.w = pack2(f1.z, f1.w);
    *(uint4*)(j.dst[z] + i) = o;
}

// ---------------- FP16 GEMM, half in, double-buffered; half or float out ----------------
struct GemmJobs {
    const __half* W[3];
    const float*  bias[3];
    const float*  res[3];
    void*         out[3];
    int           norm[3];      // 1 => fused rmsnorm+rope epilogue, half out
    int           outhalf[3];   // 1 => half out (v job)
};

__global__ __launch_bounds__(256, 2)
void gemm_fp16_kernel(const __half* __restrict__ A, GemmJobs jobs,
                      const float* __restrict__ nw, int M, int N, int K)
{
    __shared__ __align__(16) uint32_t As[2][2048];
    __shared__ __align__(16) uint32_t Bs[2][2048];

    const int z = blockIdx.z;
    const __half* W   = jobs.W[z];
    const float* bias = jobs.bias[z];
    const float* res  = jobs.res[z];
    const int    donorm = jobs.norm[z];
    const int    ohalf  = jobs.outhalf[z];

    const int tid = threadIdx.x;
    const int lane = tid & 31;
    const int wid = tid >> 5;
    const int wm = wid & 3, wn = wid >> 2;
    const int m0 = blockIdx.y * 128, n0 = blockIdx.x * 128;

    const int amt = tid >> 5, ag = (tid >> 2) & 7, aks = tid & 3;
    const int aksh = aks >> 1, ahk = aks & 1;
    const int axor = ((ag >> 1) & 1) | (aksh << 1);
    const __half* Ap = A + (size_t)(m0 + amt * 16 + ag) * K + aks * 8;
    const int bnt = ((tid >> 5) << 1) | (tid & 1);
    const int bg = (tid >> 2) & 7;
    const int bks = (tid >> 1) & 1;
    const int bxr = (tid & 1) | (bks << 1);
    const __half* Wp = W + (size_t)(n0 + bnt * 8 + bg) * K + bks * 16;

    float acc[2][8][4];
#pragma unroll
    for (int mi = 0; mi < 2; mi++)
#pragma unroll
        for (int ni = 0; ni < 8; ni++)
#pragma unroll
            for (int e = 0; e < 4; e++) acc[mi][ni][e] = 0.f;

    const int NCH = K / 32;
    uint4 a_lo = *(const uint4*)(Ap);
    uint4 a_hi = *(const uint4*)(Ap + (size_t)8 * K);
    uint4 w_lo = *(const uint4*)(Wp);
    uint4 w_hi = *(const uint4*)(Wp + 8);

    for (int kt = 0; kt < NCH; kt++) {
        const int p = kt & 1;
        {
            const uint32_t* alo = (const uint32_t*)&a_lo;
            const uint32_t* ahi = (const uint32_t*)&a_hi;
            const uint32_t* wlo = (const uint32_t*)&w_lo;
            const uint32_t* whi = (const uint32_t*)&w_hi;
#pragma unroll
            for (int t = 0; t < 4; t++) {
                int aslot = (aksh * 8 + amt) * 32 + 4 * ag + (t ^ axor);
                *(uint2*)&As[p][aslot * 4 + 2 * ahk] = make_uint2(alo[t], ahi[t]);
                int bslot = (bks * 16 + bnt) * 32 + 4 * bg + (t ^ bxr);
                *(uint2*)&Bs[p][bslot * 2] = make_uint2(wlo[t], whi[t]);
            }
        }
        __syncthreads();
        if (kt + 1 < NCH) {
            int off = (kt + 1) * 32;
            a_lo = *(const uint4*)(Ap + off);
            a_hi = *(const uint4*)(Ap + off + (size_t)8 * K);
            w_lo = *(const uint4*)(Wp + off);
            w_hi = *(const uint4*)(Wp + off + 8);
        }
#pragma unroll
        for (int ks = 0; ks < 2; ks++) {
            uint2 bb[8];
#pragma unroll
            for (int ni = 0; ni < 8; ni++) {
                int nt = wn * 8 + ni;
                int x = (nt & 1) | (ks << 1);
                int s = (ks * 16 + nt) * 32 + (lane & 28) + ((lane & 3) ^ x);
                bb[ni] = *(const uint2*)&Bs[p][s * 2];
            }
            int xa = ((lane >> 3) & 1) | (ks << 1);
            uint4 aa[2];
#pragma unroll
            for (int mi = 0; mi < 2; mi++) {
                int s = (ks * 8 + wm * 2 + mi) * 32 + (lane & 28) + ((lane & 3) ^ xa);
                aa[mi] = *(const uint4*)&As[p][s * 4];
            }
#pragma unroll
            for (int mi = 0; mi < 2; mi++)
#pragma unroll
                for (int ni = 0; ni < 8; ni++)
                    mma16(acc[mi][ni], (const uint32_t*)&aa[mi], (const uint32_t*)&bb[ni]);
        }
    }

    const int g = lane >> 2, t = lane & 3;
    if (donorm) {
        __half* Ch = (__half*)jobs.out[z];
#pragma unroll
        for (int mi = 0; mi < 2; mi++) {
#pragma unroll
            for (int h = 0; h < 2; h++) {
                int m = m0 + wm * 32 + mi * 16 + h * 8 + g;
                int s = m & (N_CTX - 1);
                float v0[8], v1[8];
                float ss = 0.f;
#pragma unroll
                for (int ni = 0; ni < 8; ni++) {
                    int n = n0 + wn * 64 + ni * 8 + 2 * t;
                    float e0 = acc[mi][ni][h * 2 + 0] + bias[n];
                    float e1 = acc[mi][ni][h * 2 + 1] + bias[n + 1];
                    v0[ni] = e0; v1[ni] = e1;
                    ss = fmaf(e0, e0, fmaf(e1, e1, ss));
                }
                ss += __shfl_xor_sync(0xffffffffu, ss, 1);
                ss += __shfl_xor_sync(0xffffffffu, ss, 2);
                float r = rsqrtf(ss * (1.0f / 64.0f) + 1.1920929e-07f);
#pragma unroll
                for (int ni = 0; ni < 8; ni++) {
                    int d = ni * 8 + 2 * t;
                    float y0 = v0[ni] * r * nw[d];
                    float y1 = v1[ni] * r * nw[d + 1];
                    int j0 = d & 31, j1 = (d + 1) & 31;
                    float o0 = y0 * g_cos[s * 32 + j0] - y1 * g_sin[s * 32 + j0];
                    float o1 = y1 * g_cos[s * 32 + j1] + y0 * g_sin[s * 32 + j1];
                    int n = n0 + wn * 64 + d;
                    *(uint32_t*)&Ch[(size_t)m * N + n] = pack2(o0, o1);
                }
            }
        }
    } else if (ohalf) {
        __half* Ch = (__half*)jobs.out[z];
#pragma unroll
        for (int mi = 0; mi < 2; mi++) {
#pragma unroll
            for (int h = 0; h < 2; h++) {
                int m = m0 + wm * 32 + mi * 16 + h * 8 + g;
#pragma unroll
                for (int ni = 0; ni < 8; ni++) {
                    int n = n0 + wn * 64 + ni * 8 + 2 * t;
                    float e0 = acc[mi][ni][h * 2 + 0];
                    float e1 = acc[mi][ni][h * 2 + 1];
                    if (bias) { e0 += bias[n]; e1 += bias[n + 1]; }
                    *(uint32_t*)&Ch[(size_t)m * N + n] = pack2(e0, e1);
                }
            }
        }
    } else {
        float* C = (float*)jobs.out[z];
#pragma unroll
        for (int mi = 0; mi < 2; mi++) {
#pragma unroll
            for (int h = 0; h < 2; h++) {
                int m = m0 + wm * 32 + mi * 16 + h * 8 + g;
#pragma unroll
                for (int ni = 0; ni < 8; ni++) {
                    int n = n0 + wn * 64 + ni * 8 + 2 * t;
                    float2 v = make_float2(acc[mi][ni][h * 2 + 0], acc[mi][ni][h * 2 + 1]);
                    if (bias) { v.x += bias[n]; v.y += bias[n + 1]; }
                    if (res) {
                        float2 r = *(const float2*)&res[(size_t)m * N + n];
                        v.x += r.x; v.y += r.y;
                    }
                    *(float2*)&C[(size_t)m * N + n] = v;
                }
            }
        }
    }
}

// ---------------- fused quadratic causal attention, FP16, double-buffered K/V ----------------
// CTA: 128 threads (4 warps), q-tile 128; warp owns 32 q-rows x full 64-k.
// Register-staged K/V double-buffer: one barrier per tile; next tile's LDGs
// overlap the current tile's mma work.
#define QH_OFF 0
#define KH_OFF 16384
#define VH_OFF (16384 + 2 * 8192)
#define ATTN_SMEM (16384 + 2 * 8192 + 2 * 9216)   /* 51200 B */

__global__ __launch_bounds__(128)
void attn_fp16_kernel(const __half* __restrict__ Q, const __half* __restrict__ Kg,
                      const __half* __restrict__ V, __half* __restrict__ Z)
{
    extern __shared__ char smc[];
    uint4* Qh = (uint4*)(smc + QH_OFF);     // [ks4][mt8][lane32]

    const int tid = threadIdx.x;
    const int lane = tid & 31;
    const int wp = tid >> 5;
    const int g = lane >> 2, t = lane & 3;
    const int bh = blockIdx.y;
    const int b = bh >> 4, h = bh & 15;
    const int jt = (int)gridDim.x - 1 - (int)blockIdx.x;   // big tiles first
    const size_t base = (size_t)(b * N_CTX) * D_MODEL + h * 64;
    const int nkt = 2 * jt + 2;

    // ---- Q tile (128 x 64 half) -> A-frag smem, once (pure repack) ----
    {
        const int qmt = tid >> 4;
        const int qg = (tid >> 1) & 7;
        const int dh = tid & 1;
        const __half* qp0 = Q + base + (size_t)(jt * 128 + qmt * 16 + qg) * D_MODEL + dh * 32;
        const __half* qp1 = qp0 + (size_t)8 * D_MODEL;
#pragma unroll
        for (int kl = 0; kl < 2; kl++) {
            int ks = dh * 2 + kl;
            uint4 A0 = *(const uint4*)(qp0 + kl * 16);
            uint4 B0 = *(const uint4*)(qp0 + kl * 16 + 8);
            uint4 A1 = *(const uint4*)(qp1 + kl * 16);
            uint4 B1 = *(const uint4*)(qp1 + kl * 16 + 8);
            const uint32_t* a0 = (const uint32_t*)&A0;
            const uint32_t* b0 = (const uint32_t*)&B0;
            const uint32_t* a1 = (const uint32_t*)&A1;
            const uint32_t* b1 = (const uint32_t*)&B1;
            int x = ((qg >> 1) & 1) | ((ks >> 1) << 1);
#pragma unroll
            for (int tt = 0; tt < 4; tt++)
                Qh[(ks * 8 + qmt) * 32 + qg * 4 + (tt ^ x)] =
                    make_uint4(a0[tt], a1[tt], b0[tt], b1[tt]);
        }
    }

    float zacc[2][8][4];
#pragma unroll
    for (int mm = 0; mm < 2; mm++)
#pragma unroll
        for (int i = 0; i < 8; i++)
#pragma unroll
            for (int j = 0; j < 4; j++) zacc[mm][i][j] = 0.f;

    const int kr = tid & 63, ksh = tid >> 6;
    const int knt = kr >> 3, kg = kr & 7;
    const int kx = (kg >> 2) | ((knt & 1) << 1);
    const int vcp = tid >> 5;
    const int vdq = (tid >> 2) & 7;
    const int vt = tid & 3;

    const __half* kbase = Kg + base + (size_t)kr * D_MODEL + ksh * 32;
    const __half* vbase = V + base + (size_t)(16 * vcp + 2 * vt) * D_MODEL + vdq * 8;

    const float inv64 = 1.0f / 64.0f;
    const int qbase = jt * 128 + wp * 32;

    // ---- prologue: load tile 0 into staging registers ----
    uint4 kA0, kB0, kA1, kB1, vA, vB, vC, vD;
    {
        kA0 = *(const uint4*)(kbase);
        kB0 = *(const uint4*)(kbase + 8);
        kA1 = *(const uint4*)(kbase + 16);
        kB1 = *(const uint4*)(kbase + 24);
        vA = *(const uint4*)(vbase);
        vB = *(const uint4*)(vbase + (size_t)1 * D_MODEL);
        vC = *(const uint4*)(vbase + (size_t)8 * D_MODEL);
        vD = *(const uint4*)(vbase + (size_t)9 * D_MODEL);
    }

    for (int kt = 0; kt < nkt; ++kt) {
        const int ktb = kt * 64;
        const int p = kt & 1;
        uint2* Kh = (uint2*)(smc + KH_OFF + p * 8192);
        uint2* Vh = (uint2*)(smc + VH_OFF + p * 9216);

        // ---- store staged K/V into buffer p ----
        {
            const uint32_t* a0 = (const uint32_t*)&kA0;
            const uint32_t* b0 = (const uint32_t*)&kB0;
            const uint32_t* a1 = (const uint32_t*)&kA1;
            const uint32_t* b1 = (const uint32_t*)&kB1;
#pragma unroll
            for (int tt = 0; tt < 4; tt++) {
                int ks0 = ksh * 2;
                Kh[(ks0 * 8 + knt) * 32 + kg * 4 + (tt ^ kx)] = make_uint2(a0[tt], b0[tt]);
                Kh[((ks0 + 1) * 8 + knt) * 32 + kg * 4 + (tt ^ kx)] = make_uint2(a1[tt], b1[tt]);
            }
            const uint32_t* a = (const uint32_t*)&vA;
            const uint32_t* bb = (const uint32_t*)&vB;
            const uint32_t* c = (const uint32_t*)&vC;
            const uint32_t* d = (const uint32_t*)&vD;
#pragma unroll
            for (int i = 0; i < 8; i++) {
                int j = i >> 1;
                uint32_t sel = (i & 1) ? 0x7632u : 0x5410u;
                Vh[(vcp * 8 + vdq) * 36 + i * 4 + vt] =
                    make_uint2(__byte_perm(a[j], bb[j], sel),
                               __byte_perm(c[j], d[j], sel));
            }
        }
        __syncthreads();   // buffer p written (also orders Q store at kt=0); buf p
                           // reads at kt-2 are behind the kt-1 barrier => no WAR hazard
        // ---- prefetch next tile's K/V (overlaps compute below) ----
        if (kt + 1 < nkt) {
            const __half* kp = kbase + (size_t)(ktb + 64) * D_MODEL;
            kA0 = *(const uint4*)(kp);
            kB0 = *(const uint4*)(kp + 8);
            kA1 = *(const uint4*)(kp + 16);
            kB1 = *(const uint4*)(kp + 24);
            const __half* vp = vbase + (size_t)(ktb + 64) * D_MODEL;
            vA = *(const uint4*)(vp);
            vB = *(const uint4*)(vp + (size_t)1 * D_MODEL);
            vC = *(const uint4*)(vp + (size_t)8 * D_MODEL);
            vD = *(const uint4*)(vp + (size_t)9 * D_MODEL);
        }

        // ---- GEMM1: S[32 x 64] per warp ----
        float sacc[2][8][4];
#pragma unroll
        for (int mm = 0; mm < 2; mm++)
#pragma unroll
            for (int i = 0; i < 8; i++)
#pragma unroll
                for (int j = 0; j < 4; j++) sacc[mm][i][j] = 0.f;

#pragma unroll
        for (int ks = 0; ks < 4; ks++) {
            int qx = ((g >> 1) & 1) | ((ks >> 1) << 1);
            uint4 qa0 = Qh[(ks * 8 + wp * 2 + 0) * 32 + g * 4 + (t ^ qx)];
            uint4 qa1 = Qh[(ks * 8 + wp * 2 + 1) * 32 + g * 4 + (t ^ qx)];
#pragma unroll
            for (int nt = 0; nt < 8; nt++) {
                int xk = (g >> 2) | ((nt & 1) << 1);
                uint2 kb = Kh[(ks * 8 + nt) * 32 + g * 4 + (t ^ xk)];
                mma16(sacc[0][nt], (const uint32_t*)&qa0, (const uint32_t*)&kb);
                mma16(sacc[1][nt], (const uint32_t*)&qa1, (const uint32_t*)&kb);
            }
        }

        // ---- P = (S/64)^2 * causal -> direct A-frag pack; GEMM2 ----
#pragma unroll
        for (int cp = 0; cp < 4; cp++) {
            uint2 vb[8];
#pragma unroll
            for (int dn = 0; dn < 8; dn++)
                vb[dn] = Vh[(cp * 8 + dn) * 36 + g * 4 + t];
#pragma unroll
            for (int mm = 0; mm < 2; mm++) {
                int qr0 = qbase + mm * 16 + g;
                int qr1 = qr0 + 8;
                int c0 = 2 * cp, c1 = 2 * cp + 1;
                int kc0 = ktb + c0 * 8 + 2 * t;
                int kc1 = ktb + c1 * 8 + 2 * t;
                float p00 = sacc[mm][c0][0] * inv64; p00 *= p00; if (kc0 > qr0)     p00 = 0.f;
                float p01 = sacc[mm][c0][1] * inv64; p01 *= p01; if (kc0 + 1 > qr0) p01 = 0.f;
                float p02 = sacc[mm][c0][2] * inv64; p02 *= p02; if (kc0 > qr1)     p02 = 0.f;
                float p03 = sacc[mm][c0][3] * inv64; p03 *= p03; if (kc0 + 1 > qr1) p03 = 0.f;
                float p10 = sacc[mm][c1][0] * inv64; p10 *= p10; if (kc1 > qr0)     p10 = 0.f;
                float p11 = sacc[mm][c1][1] * inv64; p11 *= p11; if (kc1 + 1 > qr0) p11 = 0.f;
                float p12 = sacc[mm][c1][2] * inv64; p12 *= p12; if (kc1 > qr1)     p12 = 0.f;
                float p13 = sacc[mm][c1][3] * inv64; p13 *= p13; if (kc1 + 1 > qr1) p13 = 0.f;
                uint32_t af[4];
                af[0] = pack2(p00, p01);
                af[1] = pack2(p02, p03);
                af[2] = pack2(p10, p11);
                af[3] = pack2(p12, p13);
#pragma unroll
                for (int dn = 0; dn < 8; dn++)
                    mma16(zacc[mm][dn], af, (const uint32_t*)&vb[dn]);
            }
        }
    }

    // ---- write Z (fp16) ----
#pragma unroll
    for (int mm = 0; mm < 2; mm++) {
        int qr0 = qbase + mm * 16 + g;
        int qr1 = qr0 + 8;
#pragma unroll
        for (int dn = 0; dn < 8; dn++) {
            int col = dn * 8 + 2 * t;
            *(uint32_t*)&Z[base + (size_t)qr0 * D_MODEL + col] =
                pack2(zacc[mm][dn][0], zacc[mm][dn][1]);
            *(uint32_t*)&Z[base + (size_t)qr1 * D_MODEL + col] =
                pack2(zacc[mm][dn][2], zacc[mm][dn][3]);
        }
    }
}

// ---------------- launch ----------------
extern "C" void kernel_launch(void* const* d_in, const int* in_sizes, int n_in,
                              void* d_out, int out_size)
{
    const float* x  = (const float*)d_in[0];
    const float* Wq = (const float*)d_in[1];
    const float* bq = (const float*)d_in[2];
    const float* Wk = (const float*)d_in[3];
    const float* bk = (const float*)d_in[4];
    const float* Wv = (const float*)d_in[5];
    const float* bv = (const float*)d_in[6];
    const float* Wo = (const float*)d_in[7];
    const float* nw = (const float*)d_in[8];
    float* out = (float*)d_out;

    __half *qh, *kh, *vh, *zh, *xh, *wqh, *wkh, *wvh, *woh;
    cudaGetSymbolAddress((void**)&qh,  g_qh);
    cudaGetSymbolAddress((void**)&kh,  g_kh);
    cudaGetSymbolAddress((void**)&vh,  g_vh);
    cudaGetSymbolAddress((void**)&zh,  g_zh);
    cudaGetSymbolAddress((void**)&xh,  g_xh);
    cudaGetSymbolAddress((void**)&wqh, g_wqh);
    cudaGetSymbolAddress((void**)&wkh, g_wkh);
    cudaGetSymbolAddress((void**)&wvh, g_wvh);
    cudaGetSymbolAddress((void**)&woh, g_woh);

    cudaFuncSetAttribute(attn_fp16_kernel, cudaFuncAttributeMaxDynamicSharedMemorySize, ATTN_SMEM);

    rope_cache_kernel<<<64, 1024>>>();

    // convert x + 4 weight matrices to fp16
    CvtJobs cj;
    cj.src[0] = x;  cj.dst[0] = xh;  cj.n[0] = MTOT * D_MODEL;
    cj.src[1] = Wq; cj.dst[1] = wqh; cj.n[1] = D_MODEL * D_MODEL;
    cj.src[2] = Wk; cj.dst[2] = wkh; cj.n[2] = D_MODEL * D_MODEL;
    cj.src[3] = Wv; cj.dst[3] = wvh; cj.n[3] = D_MODEL * D_MODEL;
    cj.src[4] = Wo; cj.dst[4] = woh; cj.n[4] = D_MODEL * D_MODEL;
    cvt_kernel<<<dim3(MTOT * D_MODEL / (256 * 8), 5), 256>>>(cj);

    // QKV projections: one launch, 3 jobs; q/k fused rmsnorm+rope, all half out
    GemmJobs jq;
    jq.W[0] = wqh; jq.W[1] = wkh; jq.W[2] = wvh;
    jq.bias[0] = bq; jq.bias[1] = bk; jq.bias[2] = bv;
    jq.res[0] = nullptr; jq.res[1] = nullptr; jq.res[2] = nullptr;
    jq.out[0] = qh; jq.out[1] = kh; jq.out[2] = vh;
    jq.norm[0] = 1; jq.norm[1] = 1; jq.norm[2] = 0;
    jq.outhalf[0] = 1; jq.outhalf[1] = 1; jq.outhalf[2] = 1;
    gemm_fp16_kernel<<<dim3(D_MODEL / 128, MTOT / 128, 3), 256>>>(xh, jq, nw, MTOT, D_MODEL, D_MODEL);

    attn_fp16_kernel<<<dim3(16, 32), 128, ATTN_SMEM>>>(qh, kh, vh, zh);

    // output projection + residual (fp32 out)
    GemmJobs jo;
    jo.W[0] = woh; jo.W[1] = nullptr; jo.W[2] = nullptr;
    jo.bias[0] = nullptr; jo.bias[1] = nullptr; jo.bias[2] = nullptr;
    jo.res[0] = x; jo.res[1] = nullptr; jo.res[2] = nullptr;
    jo.out[0] = out; jo.out[1] = nullptr; jo.out[2] = nullptr;
    jo.norm[0] = 0; jo.norm[1] = 0; jo.norm[2] = 0;
    jo.outhalf[0] = 0; jo.outhalf[1] = 0; jo.outhalf[2] = 0;
    gemm_fp16_kernel<<<dim3(D_MODEL / 128, MTOT / 128, 1), 256>>>(zh, jo, nw, MTOT, D_MODEL, D_MODEL);
}